// round 1
// baseline (speedup 1.0000x reference)
#include <cuda_runtime.h>
#include <math.h>

// Problem constants
#define Bc   4
#define Sc   1024
#define Dc   1024
#define Hc   16
#define DHc  64
#define Fc   4096
#define TOK  4096          // B*S
#define SIXD 6144          // 6*D

// ---------------- scratch (no allocations allowed) ----------------
__device__ float g_st[Bc * Dc];            // silu(t_emb)
__device__ float g_ada[Bc * SIXD];         // adaLN params
__device__ float g_nx[TOK * Dc];           // modulated LN output (reused)
__device__ float g_q[TOK * Dc];
__device__ float g_k[TOK * Dc];
__device__ float g_v[TOK * Dc];
__device__ float g_ao[TOK * Dc];           // attention output (pre-Wo)
__device__ float g_obr[4 * TOK * Dc];      // 4 branch outputs
__device__ float g_gate[TOK * 4];
__device__ float g_fused[TOK * Dc];
__device__ float g_xmid[TOK * Dc];         // x after first residual
__device__ float g_h1[TOK * Fc];
__device__ float g_h3[TOK * Fc];

// ---------------- elementwise helpers ----------------
__global__ void silu_k(const float* __restrict__ in, float* __restrict__ out, int n) {
    int i = blockIdx.x * blockDim.x + threadIdx.x;
    if (i < n) { float v = in[i]; out[i] = v / (1.f + __expf(-v)); }
}

// ada = silu(t_emb) @ ada_w + ada_b   (warp per output, 24576 outputs)
__global__ __launch_bounds__(256) void ada_k(const float* __restrict__ st,
                                             const float* __restrict__ W,
                                             const float* __restrict__ bias,
                                             float* __restrict__ out) {
    int o = blockIdx.x * 8 + (threadIdx.x >> 5);
    int lane = threadIdx.x & 31;
    int b = o / SIXD, n = o - b * SIXD;
    float acc = 0.f;
    for (int k = lane; k < Dc; k += 32)
        acc = fmaf(st[b * Dc + k], W[(size_t)k * SIXD + n], acc);
    #pragma unroll
    for (int off = 16; off; off >>= 1) acc += __shfl_xor_sync(~0u, acc, off);
    if (!lane) out[o] = acc + bias[n];
}

// nx = LN(x)*g+b, then *(1+sc)+sh  (block per token)
__global__ __launch_bounds__(256) void ln_mod_k(const float* __restrict__ X,
                                                const float* __restrict__ gam,
                                                const float* __restrict__ bet,
                                                const float* __restrict__ ada,
                                                int sh_off, int sc_off,
                                                float* __restrict__ out) {
    int t = blockIdx.x;
    int b = t >> 10;
    int tid = threadIdx.x;
    const float* xr = X + (size_t)t * Dc;
    float s = 0.f, ss = 0.f;
    for (int i = tid; i < Dc; i += 256) { float v = xr[i]; s += v; ss = fmaf(v, v, ss); }
    __shared__ float r1[8], r2[8];
    __shared__ float muS, rsS;
    #pragma unroll
    for (int off = 16; off; off >>= 1) {
        s  += __shfl_xor_sync(~0u, s,  off);
        ss += __shfl_xor_sync(~0u, ss, off);
    }
    if ((tid & 31) == 0) { r1[tid >> 5] = s; r2[tid >> 5] = ss; }
    __syncthreads();
    if (tid < 32) {
        float a = (tid < 8) ? r1[tid] : 0.f;
        float c = (tid < 8) ? r2[tid] : 0.f;
        #pragma unroll
        for (int off = 4; off; off >>= 1) {
            a += __shfl_xor_sync(~0u, a, off);
            c += __shfl_xor_sync(~0u, c, off);
        }
        if (tid == 0) {
            float mu = a * (1.f / Dc);
            float var = c * (1.f / Dc) - mu * mu;
            muS = mu; rsS = rsqrtf(var + 1e-6f);
        }
    }
    __syncthreads();
    float mu = muS, rs = rsS;
    const float* ar = ada + b * SIXD;
    float* orow = out + (size_t)t * Dc;
    for (int i = tid; i < Dc; i += 256) {
        float v = (xr[i] - mu) * rs * gam[i] + bet[i];
        orow[i] = fmaf(v, 1.f + ar[sc_off + i], ar[sh_off + i]);
    }
}

// ---------------- tiled fp32 GEMM: C = A[M,K] @ B[K,N] ----------------
// M%128==0, N%128==0, K%16==0 guaranteed by call sites.
// If resid != nullptr: C[t,n] = resid[t,n] + gate[(t>>10)*6144 + n] * acc
__global__ __launch_bounds__(256) void gemm_k(const float* __restrict__ A,
                                              const float* __restrict__ B,
                                              float* __restrict__ C,
                                              int M, int N, int K,
                                              const float* __restrict__ resid,
                                              const float* __restrict__ gate) {
    __shared__ float As[16][128];
    __shared__ float Bs[16][128];
    int tid = threadIdx.x;
    int bx = blockIdx.x, by = blockIdx.y;
    int tx = tid & 15, ty = tid >> 4;
    float acc[8][8];
    #pragma unroll
    for (int i = 0; i < 8; i++)
        #pragma unroll
        for (int j = 0; j < 8; j++) acc[i][j] = 0.f;

    int aRow = tid >> 2, aCol = (tid & 3) << 2;
    int bRow = tid >> 5, bCol = (tid & 31) << 2;
    const float* Ag = A + (size_t)(by * 128) * K;
    const float* Bg = B + bx * 128;

    for (int k0 = 0; k0 < K; k0 += 16) {
        float4 a0 = *(const float4*)(Ag + (size_t)aRow * K + k0 + aCol);
        float4 a1 = *(const float4*)(Ag + (size_t)(aRow + 64) * K + k0 + aCol);
        float4 b0 = *(const float4*)(Bg + (size_t)(k0 + bRow) * N + bCol);
        float4 b1 = *(const float4*)(Bg + (size_t)(k0 + bRow + 8) * N + bCol);
        As[aCol + 0][aRow] = a0.x; As[aCol + 1][aRow] = a0.y;
        As[aCol + 2][aRow] = a0.z; As[aCol + 3][aRow] = a0.w;
        As[aCol + 0][aRow + 64] = a1.x; As[aCol + 1][aRow + 64] = a1.y;
        As[aCol + 2][aRow + 64] = a1.z; As[aCol + 3][aRow + 64] = a1.w;
        *(float4*)&Bs[bRow][bCol]     = b0;
        *(float4*)&Bs[bRow + 8][bCol] = b1;
        __syncthreads();
        #pragma unroll
        for (int kk = 0; kk < 16; kk++) {
            float ar[8], br[8];
            *(float4*)(ar)     = *(const float4*)&As[kk][ty * 8];
            *(float4*)(ar + 4) = *(const float4*)&As[kk][ty * 8 + 4];
            *(float4*)(br)     = *(const float4*)&Bs[kk][tx * 8];
            *(float4*)(br + 4) = *(const float4*)&Bs[kk][tx * 8 + 4];
            #pragma unroll
            for (int i = 0; i < 8; i++)
                #pragma unroll
                for (int j = 0; j < 8; j++)
                    acc[i][j] = fmaf(ar[i], br[j], acc[i][j]);
        }
        __syncthreads();
    }

    #pragma unroll
    for (int i = 0; i < 8; i++) {
        int row = by * 128 + ty * 8 + i;
        int col = bx * 128 + tx * 8;
        size_t base = (size_t)row * N + col;
        if (resid == nullptr) {
            float4 o0 = make_float4(acc[i][0], acc[i][1], acc[i][2], acc[i][3]);
            float4 o1 = make_float4(acc[i][4], acc[i][5], acc[i][6], acc[i][7]);
            *(float4*)&C[base]     = o0;
            *(float4*)&C[base + 4] = o1;
        } else {
            int b = row >> 10;
            const float* gr = gate + (size_t)b * SIXD + col;
            float4 r0 = *(const float4*)&resid[base];
            float4 r1 = *(const float4*)&resid[base + 4];
            float4 g0 = *(const float4*)&gr[0];
            float4 g1 = *(const float4*)&gr[4];
            float4 o0 = make_float4(fmaf(g0.x, acc[i][0], r0.x), fmaf(g0.y, acc[i][1], r0.y),
                                    fmaf(g0.z, acc[i][2], r0.z), fmaf(g0.w, acc[i][3], r0.w));
            float4 o1 = make_float4(fmaf(g1.x, acc[i][4], r1.x), fmaf(g1.y, acc[i][5], r1.y),
                                    fmaf(g1.z, acc[i][6], r1.z), fmaf(g1.w, acc[i][7], r1.w));
            *(float4*)&C[base]     = o0;
            *(float4*)&C[base + 4] = o1;
        }
    }
}

// ---------------- fused flash-style attention ----------------
// grid: (S/8, B*H); 256 threads = 8 warps; warp per query; 32-key smem tiles.
// branch: 0=grid(-dist), 1=reg(|d|<=1), 2=ent(pair), 3=sem(none)
__global__ __launch_bounds__(256) void attn_k(const float* __restrict__ Q,
                                              const float* __restrict__ Km,
                                              const float* __restrict__ Vm,
                                              float* __restrict__ O, int branch) {
    __shared__ float Qs[8][68];
    __shared__ float Ks[32][68];
    __shared__ float Vs[32][68];
    int tid = threadIdx.x, lane = tid & 31, w = tid >> 5;
    int bh = blockIdx.y;
    int b = bh >> 4, h = bh & 15;
    int q0 = blockIdx.x << 3;
    size_t headoff = (size_t)h * DHc;

    if (tid < 128) {
        int r = tid >> 4, c = (tid & 15) << 2;
        *(float4*)&Qs[r][c] =
            *(const float4*)&Q[((size_t)(b * Sc + q0 + r)) * Dc + headoff + c];
    }
    int qi = q0 + w;
    float m = -INFINITY, l = 0.f, o0 = 0.f, o1 = 0.f;

    int lr = tid >> 4;            // 0..15
    int lc = (tid & 15) << 2;     // 0..60

    for (int t0 = 0; t0 < Sc; t0 += 32) {
        __syncthreads();  // prior compute (and Q load on iter 0) done
        size_t g0i = ((size_t)(b * Sc + t0 + lr)) * Dc + headoff + lc;
        size_t g1i = g0i + (size_t)16 * Dc;
        *(float4*)&Ks[lr][lc]      = *(const float4*)&Km[g0i];
        *(float4*)&Vs[lr][lc]      = *(const float4*)&Vm[g0i];
        *(float4*)&Ks[lr + 16][lc] = *(const float4*)&Km[g1i];
        *(float4*)&Vs[lr + 16][lc] = *(const float4*)&Vm[g1i];
        __syncthreads();

        float s = 0.f;
        #pragma unroll
        for (int d = 0; d < 64; d += 4) {
            float4 qv = *(const float4*)&Qs[w][d];
            float4 kv = *(const float4*)&Ks[lane][d];
            s = fmaf(qv.x, kv.x, s);
            s = fmaf(qv.y, kv.y, s);
            s = fmaf(qv.z, kv.z, s);
            s = fmaf(qv.w, kv.w, s);
        }
        int kj = t0 + lane;
        s *= 0.125f;  // 1/sqrt(64)
        int dist = abs(qi - kj);
        if (branch == 0)      s -= (float)dist;
        else if (branch == 1) { if (dist > 1) s -= 1e9f; }
        else if (branch == 2) { if ((qi >> 1) != (kj >> 1)) s -= 1e9f; }

        float tm = s;
        #pragma unroll
        for (int off = 16; off; off >>= 1)
            tm = fmaxf(tm, __shfl_xor_sync(~0u, tm, off));
        float mn = fmaxf(m, tm);
        float p = __expf(s - mn);
        float corr = __expf(m - mn);   // exp(-inf)=0 on first tile
        m = mn;
        float tsum = p;
        #pragma unroll
        for (int off = 16; off; off >>= 1)
            tsum += __shfl_xor_sync(~0u, tsum, off);
        l = fmaf(l, corr, tsum);
        o0 *= corr; o1 *= corr;
        #pragma unroll
        for (int j = 0; j < 32; j++) {
            float pj = __shfl_sync(~0u, p, j);
            o0 = fmaf(pj, Vs[j][lane], o0);
            o1 = fmaf(pj, Vs[j][lane + 32], o1);
        }
    }
    float inv = 1.f / l;
    size_t ob = ((size_t)(b * Sc + qi)) * Dc + headoff;
    O[ob + lane]      = o0 * inv;
    O[ob + 32 + lane] = o1 * inv;
}

// ---------------- fusion gate: softmax(cat(o1..o4) @ wg + bg) ----------------
__global__ __launch_bounds__(256) void gate_k(const float* __restrict__ Ob,
                                              const float* __restrict__ wg,
                                              const float* __restrict__ bg,
                                              float* __restrict__ gate) {
    int t = blockIdx.x, tid = threadIdx.x;
    float4 acc = make_float4(0.f, 0.f, 0.f, 0.f);
    for (int d = tid; d < 4 * Dc; d += 256) {
        int p = d >> 10, dd = d & 1023;
        float v = Ob[((size_t)p * TOK + t) * Dc + dd];
        float4 wv = *(const float4*)&wg[(size_t)d * 4];
        acc.x = fmaf(v, wv.x, acc.x);
        acc.y = fmaf(v, wv.y, acc.y);
        acc.z = fmaf(v, wv.z, acc.z);
        acc.w = fmaf(v, wv.w, acc.w);
    }
    #pragma unroll
    for (int off = 16; off; off >>= 1) {
        acc.x += __shfl_xor_sync(~0u, acc.x, off);
        acc.y += __shfl_xor_sync(~0u, acc.y, off);
        acc.z += __shfl_xor_sync(~0u, acc.z, off);
        acc.w += __shfl_xor_sync(~0u, acc.w, off);
    }
    __shared__ float4 red[8];
    if ((tid & 31) == 0) red[tid >> 5] = acc;
    __syncthreads();
    if (tid == 0) {
        float4 a = red[0];
        #pragma unroll
        for (int i = 1; i < 8; i++) {
            a.x += red[i].x; a.y += red[i].y; a.z += red[i].z; a.w += red[i].w;
        }
        float l0 = a.x + bg[0], l1 = a.y + bg[1], l2 = a.z + bg[2], l3 = a.w + bg[3];
        float mx = fmaxf(fmaxf(l0, l1), fmaxf(l2, l3));
        float e0 = __expf(l0 - mx), e1 = __expf(l1 - mx),
              e2 = __expf(l2 - mx), e3 = __expf(l3 - mx);
        float inv = 1.f / (e0 + e1 + e2 + e3);
        gate[t * 4 + 0] = e0 * inv; gate[t * 4 + 1] = e1 * inv;
        gate[t * 4 + 2] = e2 * inv; gate[t * 4 + 3] = e3 * inv;
    }
}

__global__ void fusemix_k(const float* __restrict__ Ob,
                          const float* __restrict__ gate,
                          float* __restrict__ out) {
    int idx = blockIdx.x * 256 + threadIdx.x;  // TOK*Dc total
    int t = idx >> 10;
    float g0 = gate[t * 4 + 0], g1 = gate[t * 4 + 1];
    float g2 = gate[t * 4 + 2], g3 = gate[t * 4 + 3];
    const size_t P = (size_t)TOK * Dc;
    out[idx] = g0 * Ob[idx] + g1 * Ob[idx + P] + g2 * Ob[idx + 2 * P] + g3 * Ob[idx + 3 * P];
}

__global__ void swiglu_k(const float* __restrict__ h1,
                         const float* __restrict__ h3,
                         float* __restrict__ out, size_t n) {
    size_t i = (size_t)blockIdx.x * 256 + threadIdx.x;
    if (i < n) {
        float a = h1[i];
        out[i] = (a / (1.f + __expf(-a))) * h3[i];
    }
}

// ---------------- host launch ----------------
extern "C" void kernel_launch(void* const* d_in, const int* in_sizes, int n_in,
                              void* d_out, int out_size) {
    const float* x      = (const float*)d_in[0];
    const float* t_emb  = (const float*)d_in[1];
    const float* ln1_g  = (const float*)d_in[2];
    const float* ln1_b  = (const float*)d_in[3];
    const float* ln2_g  = (const float*)d_in[4];
    const float* ln2_b  = (const float*)d_in[5];
    const float* ada_w  = (const float*)d_in[6];
    const float* ada_b  = (const float*)d_in[7];

    // Disambiguate input ordering: dict order has fus_wg (16384 elems) at idx 8,
    // signature order has grid_wq (1048576 elems) at idx 8.
    const float *fus_wg, *fus_bg, *fus_wo, *ffn_w1, *ffn_w2, *ffn_w3;
    int ab;  // base index of attention weights
    if (in_sizes[8] == 16384) {
        fus_wg = (const float*)d_in[8];  fus_bg = (const float*)d_in[9];
        fus_wo = (const float*)d_in[10];
        ffn_w1 = (const float*)d_in[11]; ffn_w2 = (const float*)d_in[12];
        ffn_w3 = (const float*)d_in[13];
        ab = 14;
    } else {
        ab = 8;
        fus_wg = (const float*)d_in[24]; fus_bg = (const float*)d_in[25];
        fus_wo = (const float*)d_in[26];
        ffn_w1 = (const float*)d_in[27]; ffn_w2 = (const float*)d_in[28];
        ffn_w3 = (const float*)d_in[29];
    }

    float *st, *ada, *nx, *q, *k, *v, *ao, *obr, *gate, *fused, *xmid, *h1, *h3;
    cudaGetSymbolAddress((void**)&st,    g_st);
    cudaGetSymbolAddress((void**)&ada,   g_ada);
    cudaGetSymbolAddress((void**)&nx,    g_nx);
    cudaGetSymbolAddress((void**)&q,     g_q);
    cudaGetSymbolAddress((void**)&k,     g_k);
    cudaGetSymbolAddress((void**)&v,     g_v);
    cudaGetSymbolAddress((void**)&ao,    g_ao);
    cudaGetSymbolAddress((void**)&obr,   g_obr);
    cudaGetSymbolAddress((void**)&gate,  g_gate);
    cudaGetSymbolAddress((void**)&fused, g_fused);
    cudaGetSymbolAddress((void**)&xmid,  g_xmid);
    cudaGetSymbolAddress((void**)&h1,    g_h1);
    cudaGetSymbolAddress((void**)&h3,    g_h3);

    float* out = (float*)d_out;

    // 1. AdaLN parameters
    silu_k<<<(Bc * Dc + 255) / 256, 256>>>(t_emb, st, Bc * Dc);
    ada_k<<<(Bc * SIXD) / 8, 256>>>(st, ada_w, ada_b, ada);

    // 2. nx = modulated LN(x)   (sh_m at 0, sc_m at D)
    ln_mod_k<<<TOK, 256>>>(x, ln1_g, ln1_b, ada, 0, Dc, nx);

    // 3. four attention branches
    dim3 gProj(Dc / 128, TOK / 128);   // (8,32)
    dim3 gAttn(Sc / 8, Bc * Hc);       // (128,64)
    for (int p = 0; p < 4; p++) {
        const float* wq = (const float*)d_in[ab + p * 4 + 0];
        const float* wk = (const float*)d_in[ab + p * 4 + 1];
        const float* wv = (const float*)d_in[ab + p * 4 + 2];
        const float* wo = (const float*)d_in[ab + p * 4 + 3];
        gemm_k<<<gProj, 256>>>(nx, wq, q, TOK, Dc, Dc, nullptr, nullptr);
        gemm_k<<<gProj, 256>>>(nx, wk, k, TOK, Dc, Dc, nullptr, nullptr);
        gemm_k<<<gProj, 256>>>(nx, wv, v, TOK, Dc, Dc, nullptr, nullptr);
        attn_k<<<gAttn, 256>>>(q, k, v, ao, p);
        gemm_k<<<gProj, 256>>>(ao, wo, obr + (size_t)p * TOK * Dc, TOK, Dc, Dc,
                               nullptr, nullptr);
    }

    // 4. learned fusion + first residual (g_m at 2D)
    gate_k<<<TOK, 256>>>(obr, fus_wg, fus_bg, gate);
    fusemix_k<<<(TOK * Dc) / 256, 256>>>(obr, gate, fused);
    gemm_k<<<gProj, 256>>>(fused, fus_wo, xmid, TOK, Dc, Dc, x, ada + 2 * Dc);

    // 5. FFN with AdaLN (sh_f at 3D, sc_f at 4D, g_f at 5D)
    ln_mod_k<<<TOK, 256>>>(xmid, ln2_g, ln2_b, ada, 3 * Dc, 4 * Dc, nx);
    dim3 gFfnUp(Fc / 128, TOK / 128);    // (32,32)
    gemm_k<<<gFfnUp, 256>>>(nx, ffn_w1, h1, TOK, Fc, Dc, nullptr, nullptr);
    gemm_k<<<gFfnUp, 256>>>(nx, ffn_w3, h3, TOK, Fc, Dc, nullptr, nullptr);
    size_t nf = (size_t)TOK * Fc;
    swiglu_k<<<(unsigned)((nf + 255) / 256), 256>>>(h1, h3, h1, nf);
    gemm_k<<<gProj, 256>>>(h1, ffn_w2, out, TOK, Dc, Fc, xmid, ada + 5 * Dc);
}

// round 2
// speedup vs baseline: 2.1412x; 2.1412x over previous
#include <cuda_runtime.h>
#include <math.h>
#include <stdint.h>

// Problem constants
#define Bc   4
#define Sc   1024
#define Dc   1024
#define Hc   16
#define DHc  64
#define Fc   4096
#define TOK  4096          // B*S
#define SIXD 6144          // 6*D

// ---------------- scratch (no allocations allowed) ----------------
__device__ float g_st[Bc * Dc];            // silu(t_emb)
__device__ float g_ada[Bc * SIXD];         // adaLN params
__device__ float g_nx[TOK * Dc];           // modulated LN output (reused)
__device__ float g_q[TOK * Dc];
__device__ float g_k[TOK * Dc];
__device__ float g_v[TOK * Dc];
__device__ float g_ao[TOK * Dc];           // attention output (pre-Wo)
__device__ float g_obr[4 * TOK * Dc];      // 4 branch outputs
__device__ float g_gate[TOK * 4];
__device__ float g_fused[TOK * Dc];
__device__ float g_xmid[TOK * Dc];         // x after first residual
__device__ float g_h1[TOK * Fc];
__device__ float g_h3[TOK * Fc];

// ---------------- elementwise helpers ----------------
__global__ void silu_k(const float* __restrict__ in, float* __restrict__ out, int n) {
    int i = blockIdx.x * blockDim.x + threadIdx.x;
    if (i < n) { float v = in[i]; out[i] = v / (1.f + __expf(-v)); }
}

// ada = silu(t_emb) @ ada_w + ada_b   (warp per output, 24576 outputs)
__global__ __launch_bounds__(256) void ada_k(const float* __restrict__ st,
                                             const float* __restrict__ W,
                                             const float* __restrict__ bias,
                                             float* __restrict__ out) {
    int o = blockIdx.x * 8 + (threadIdx.x >> 5);
    int lane = threadIdx.x & 31;
    int b = o / SIXD, n = o - b * SIXD;
    float acc = 0.f;
    for (int k = lane; k < Dc; k += 32)
        acc = fmaf(st[b * Dc + k], W[(size_t)k * SIXD + n], acc);
    #pragma unroll
    for (int off = 16; off; off >>= 1) acc += __shfl_xor_sync(~0u, acc, off);
    if (!lane) out[o] = acc + bias[n];
}

// nx = LN(x)*g+b, then *(1+sc)+sh  (block per token)
__global__ __launch_bounds__(256) void ln_mod_k(const float* __restrict__ X,
                                                const float* __restrict__ gam,
                                                const float* __restrict__ bet,
                                                const float* __restrict__ ada,
                                                int sh_off, int sc_off,
                                                float* __restrict__ out) {
    int t = blockIdx.x;
    int b = t >> 10;
    int tid = threadIdx.x;
    const float* xr = X + (size_t)t * Dc;
    float s = 0.f, ss = 0.f;
    for (int i = tid; i < Dc; i += 256) { float v = xr[i]; s += v; ss = fmaf(v, v, ss); }
    __shared__ float r1[8], r2[8];
    __shared__ float muS, rsS;
    #pragma unroll
    for (int off = 16; off; off >>= 1) {
        s  += __shfl_xor_sync(~0u, s,  off);
        ss += __shfl_xor_sync(~0u, ss, off);
    }
    if ((tid & 31) == 0) { r1[tid >> 5] = s; r2[tid >> 5] = ss; }
    __syncthreads();
    if (tid < 32) {
        float a = (tid < 8) ? r1[tid] : 0.f;
        float c = (tid < 8) ? r2[tid] : 0.f;
        #pragma unroll
        for (int off = 4; off; off >>= 1) {
            a += __shfl_xor_sync(~0u, a, off);
            c += __shfl_xor_sync(~0u, c, off);
        }
        if (tid == 0) {
            float mu = a * (1.f / Dc);
            float var = c * (1.f / Dc) - mu * mu;
            muS = mu; rsS = rsqrtf(var + 1e-6f);
        }
    }
    __syncthreads();
    float mu = muS, rs = rsS;
    const float* ar = ada + b * SIXD;
    float* orow = out + (size_t)t * Dc;
    for (int i = tid; i < Dc; i += 256) {
        float v = (xr[i] - mu) * rs * gam[i] + bet[i];
        orow[i] = fmaf(v, 1.f + ar[sc_off + i], ar[sh_off + i]);
    }
}

// ---------------- TF32 tensor-core GEMM: C = A[M,K] @ B[K,N] ----------------
// 128x128 block tile, 8 warps of 64x32, mma.sync m16n8k8 tf32.
// If resid != nullptr: C[t,n] = resid[t,n] + gate[(t>>10)*6144 + n] * acc

__device__ __forceinline__ float to_tf32(float x) {
    float r;
    asm("cvt.rna.tf32.f32 %0, %1;" : "=f"(r) : "f"(x));
    return r;
}

__device__ __forceinline__ void mma_tf32(float* c, uint32_t a0, uint32_t a1,
                                         uint32_t a2, uint32_t a3,
                                         uint32_t b0, uint32_t b1) {
    asm("mma.sync.aligned.m16n8k8.row.col.f32.tf32.tf32.f32 "
        "{%0,%1,%2,%3},{%4,%5,%6,%7},{%8,%9},{%0,%1,%2,%3};"
        : "+f"(c[0]), "+f"(c[1]), "+f"(c[2]), "+f"(c[3])
        : "r"(a0), "r"(a1), "r"(a2), "r"(a3), "r"(b0), "r"(b1));
}

#define SPAD 136  // row padding: bank = (8k + m) & 31 -> conflict-free gathers

__global__ __launch_bounds__(256) void gemm_tc(const float* __restrict__ A,
                                               const float* __restrict__ B,
                                               float* __restrict__ C,
                                               int M, int N, int K,
                                               const float* __restrict__ resid,
                                               const float* __restrict__ gate) {
    __shared__ float As[16][SPAD];   // [k][m]
    __shared__ float Bs[16][SPAD];   // [k][n]
    int tid = threadIdx.x;
    int bx = blockIdx.x, by = blockIdx.y;
    int w = tid >> 5, lane = tid & 31;
    int wm = (w >> 2) * 64, wn = (w & 3) * 32;
    int g = lane >> 2, t = lane & 3;

    float acc[4][4][4];
    #pragma unroll
    for (int i = 0; i < 4; i++)
        #pragma unroll
        for (int j = 0; j < 4; j++)
            #pragma unroll
            for (int r = 0; r < 4; r++) acc[i][j][r] = 0.f;

    int aRow = tid >> 2, aCol = (tid & 3) << 2;
    int bRow = tid >> 5, bCol = (tid & 31) << 2;
    const float* Ag = A + (size_t)(by * 128) * K;
    const float* Bg = B + bx * 128;
    const uint32_t* Asu = (const uint32_t*)&As[0][0];
    const uint32_t* Bsu = (const uint32_t*)&Bs[0][0];

    for (int k0 = 0; k0 < K; k0 += 16) {
        float4 a0 = *(const float4*)(Ag + (size_t)aRow * K + k0 + aCol);
        float4 a1 = *(const float4*)(Ag + (size_t)(aRow + 64) * K + k0 + aCol);
        float4 b0 = *(const float4*)(Bg + (size_t)(k0 + bRow) * N + bCol);
        float4 b1 = *(const float4*)(Bg + (size_t)(k0 + bRow + 8) * N + bCol);
        As[aCol + 0][aRow] = to_tf32(a0.x); As[aCol + 1][aRow] = to_tf32(a0.y);
        As[aCol + 2][aRow] = to_tf32(a0.z); As[aCol + 3][aRow] = to_tf32(a0.w);
        As[aCol + 0][aRow + 64] = to_tf32(a1.x); As[aCol + 1][aRow + 64] = to_tf32(a1.y);
        As[aCol + 2][aRow + 64] = to_tf32(a1.z); As[aCol + 3][aRow + 64] = to_tf32(a1.w);
        {
            float4 c0 = make_float4(to_tf32(b0.x), to_tf32(b0.y), to_tf32(b0.z), to_tf32(b0.w));
            float4 c1 = make_float4(to_tf32(b1.x), to_tf32(b1.y), to_tf32(b1.z), to_tf32(b1.w));
            *(float4*)&Bs[bRow][bCol]     = c0;
            *(float4*)&Bs[bRow + 8][bCol] = c1;
        }
        __syncthreads();

        #pragma unroll
        for (int ks = 0; ks < 16; ks += 8) {
            uint32_t af[4][4], bf[4][2];
            int kLo = ks + t, kHi = ks + t + 4;
            #pragma unroll
            for (int i = 0; i < 4; i++) {
                int m0 = wm + 16 * i + g;
                af[i][0] = Asu[kLo * SPAD + m0];
                af[i][1] = Asu[kLo * SPAD + m0 + 8];
                af[i][2] = Asu[kHi * SPAD + m0];
                af[i][3] = Asu[kHi * SPAD + m0 + 8];
            }
            #pragma unroll
            for (int j = 0; j < 4; j++) {
                int n0 = wn + 8 * j + g;
                bf[j][0] = Bsu[kLo * SPAD + n0];
                bf[j][1] = Bsu[kHi * SPAD + n0];
            }
            #pragma unroll
            for (int i = 0; i < 4; i++)
                #pragma unroll
                for (int j = 0; j < 4; j++)
                    mma_tf32(acc[i][j], af[i][0], af[i][1], af[i][2], af[i][3],
                             bf[j][0], bf[j][1]);
        }
        __syncthreads();
    }

    // epilogue: c0:(g,2t) c1:(g,2t+1) c2:(g+8,2t) c3:(g+8,2t+1)
    #pragma unroll
    for (int i = 0; i < 4; i++) {
        #pragma unroll
        for (int j = 0; j < 4; j++) {
            int row0 = by * 128 + wm + 16 * i + g;
            int col  = bx * 128 + wn + 8 * j + 2 * t;
            size_t b0i = (size_t)row0 * N + col;
            size_t b1i = (size_t)(row0 + 8) * N + col;
            if (resid == nullptr) {
                *(float2*)&C[b0i] = make_float2(acc[i][j][0], acc[i][j][1]);
                *(float2*)&C[b1i] = make_float2(acc[i][j][2], acc[i][j][3]);
            } else {
                int bb0 = row0 >> 10, bb1 = (row0 + 8) >> 10;
                float2 gr0 = *(const float2*)&gate[(size_t)bb0 * SIXD + col];
                float2 gr1 = *(const float2*)&gate[(size_t)bb1 * SIXD + col];
                float2 r0 = *(const float2*)&resid[b0i];
                float2 r1 = *(const float2*)&resid[b1i];
                *(float2*)&C[b0i] = make_float2(fmaf(gr0.x, acc[i][j][0], r0.x),
                                                fmaf(gr0.y, acc[i][j][1], r0.y));
                *(float2*)&C[b1i] = make_float2(fmaf(gr1.x, acc[i][j][2], r1.x),
                                                fmaf(gr1.y, acc[i][j][3], r1.y));
            }
        }
    }
}

// ---------------- fused flash-style attention (full branches) ----------------
// branch: 0=grid(-dist), 3=sem(none)
__global__ __launch_bounds__(256) void attn_k(const float* __restrict__ Q,
                                              const float* __restrict__ Km,
                                              const float* __restrict__ Vm,
                                              float* __restrict__ O, int branch) {
    __shared__ float Qs[8][68];
    __shared__ float Ks[32][68];
    __shared__ float Vs[32][68];
    int tid = threadIdx.x, lane = tid & 31, w = tid >> 5;
    int bh = blockIdx.y;
    int b = bh >> 4, h = bh & 15;
    int q0 = blockIdx.x << 3;
    size_t headoff = (size_t)h * DHc;

    if (tid < 128) {
        int r = tid >> 4, c = (tid & 15) << 2;
        *(float4*)&Qs[r][c] =
            *(const float4*)&Q[((size_t)(b * Sc + q0 + r)) * Dc + headoff + c];
    }
    int qi = q0 + w;
    float m = -INFINITY, l = 0.f, o0 = 0.f, o1 = 0.f;

    int lr = tid >> 4;
    int lc = (tid & 15) << 2;

    for (int t0 = 0; t0 < Sc; t0 += 32) {
        __syncthreads();
        size_t g0i = ((size_t)(b * Sc + t0 + lr)) * Dc + headoff + lc;
        size_t g1i = g0i + (size_t)16 * Dc;
        *(float4*)&Ks[lr][lc]      = *(const float4*)&Km[g0i];
        *(float4*)&Vs[lr][lc]      = *(const float4*)&Vm[g0i];
        *(float4*)&Ks[lr + 16][lc] = *(const float4*)&Km[g1i];
        *(float4*)&Vs[lr + 16][lc] = *(const float4*)&Vm[g1i];
        __syncthreads();

        float s = 0.f;
        #pragma unroll
        for (int d = 0; d < 64; d += 4) {
            float4 qv = *(const float4*)&Qs[w][d];
            float4 kv = *(const float4*)&Ks[lane][d];
            s = fmaf(qv.x, kv.x, s);
            s = fmaf(qv.y, kv.y, s);
            s = fmaf(qv.z, kv.z, s);
            s = fmaf(qv.w, kv.w, s);
        }
        int kj = t0 + lane;
        s *= 0.125f;
        if (branch == 0) s -= (float)abs(qi - kj);

        float tm = s;
        #pragma unroll
        for (int off = 16; off; off >>= 1)
            tm = fmaxf(tm, __shfl_xor_sync(~0u, tm, off));
        float mn = fmaxf(m, tm);
        float p = __expf(s - mn);
        float corr = __expf(m - mn);
        m = mn;
        float tsum = p;
        #pragma unroll
        for (int off = 16; off; off >>= 1)
            tsum += __shfl_xor_sync(~0u, tsum, off);
        l = fmaf(l, corr, tsum);
        o0 *= corr; o1 *= corr;
        #pragma unroll
        for (int j = 0; j < 32; j++) {
            float pj = __shfl_sync(~0u, p, j);
            o0 = fmaf(pj, Vs[j][lane], o0);
            o1 = fmaf(pj, Vs[j][lane + 32], o1);
        }
    }
    float inv = 1.f / l;
    size_t ob = ((size_t)(b * Sc + qi)) * Dc + headoff;
    O[ob + lane]      = o0 * inv;
    O[ob + 32 + lane] = o1 * inv;
}

// ---------------- sparse attention for masked branches ----------------
// mode 1 = reg: keys {q-1,q,q+1} (clamped). mode 2 = ent: keys {2*(q/2), +1}.
// Masked keys contribute exp(-1e9 + small) == 0 in fp32, so restricting the
// softmax to valid keys is exact.
__global__ __launch_bounds__(128) void attn_sparse_k(const float* __restrict__ Q,
                                                     const float* __restrict__ Km,
                                                     const float* __restrict__ Vm,
                                                     float* __restrict__ O, int mode) {
    int w = threadIdx.x >> 5, lane = threadIdx.x & 31;
    int qi = blockIdx.x * 4 + w;
    int bh = blockIdx.y;
    int b = bh >> 4, h = bh & 15;
    size_t rowbase = ((size_t)(b * Sc + qi)) * Dc + (size_t)h * DHc;
    float q0 = Q[rowbase + lane], q1 = Q[rowbase + 32 + lane];

    int k0i, nk;
    if (mode == 1) {
        k0i = qi - 1; nk = 3;
        if (qi == 0)      { k0i = 0; nk = 2; }
        if (qi == Sc - 1) { nk = 2; }
    } else {
        k0i = qi & ~1; nk = 2;
    }

    float s[3] = {0.f, 0.f, 0.f};
    #pragma unroll 3
    for (int kk = 0; kk < 3; kk++) {
        if (kk < nk) {
            size_t kb = ((size_t)(b * Sc + k0i + kk)) * Dc + (size_t)h * DHc;
            float acc = fmaf(q0, Km[kb + lane], q1 * Km[kb + 32 + lane]);
            #pragma unroll
            for (int off = 16; off; off >>= 1)
                acc += __shfl_xor_sync(~0u, acc, off);
            s[kk] = acc * 0.125f;
        }
    }
    float mx = s[0];
    for (int kk = 1; kk < nk; kk++) mx = fmaxf(mx, s[kk]);
    float p[3], l = 0.f;
    for (int kk = 0; kk < nk; kk++) { p[kk] = __expf(s[kk] - mx); l += p[kk]; }
    float inv = 1.f / l;

    float o0 = 0.f, o1 = 0.f;
    #pragma unroll 3
    for (int kk = 0; kk < 3; kk++) {
        if (kk < nk) {
            size_t vb = ((size_t)(b * Sc + k0i + kk)) * Dc + (size_t)h * DHc;
            o0 = fmaf(p[kk], Vm[vb + lane], o0);
            o1 = fmaf(p[kk], Vm[vb + 32 + lane], o1);
        }
    }
    O[rowbase + lane]      = o0 * inv;
    O[rowbase + 32 + lane] = o1 * inv;
}

// ---------------- fusion gate: softmax(cat(o1..o4) @ wg + bg) ----------------
__global__ __launch_bounds__(256) void gate_k(const float* __restrict__ Ob,
                                              const float* __restrict__ wg,
                                              const float* __restrict__ bg,
                                              float* __restrict__ gate) {
    int t = blockIdx.x, tid = threadIdx.x;
    float4 acc = make_float4(0.f, 0.f, 0.f, 0.f);
    for (int d = tid; d < 4 * Dc; d += 256) {
        int p = d >> 10, dd = d & 1023;
        float v = Ob[((size_t)p * TOK + t) * Dc + dd];
        float4 wv = *(const float4*)&wg[(size_t)d * 4];
        acc.x = fmaf(v, wv.x, acc.x);
        acc.y = fmaf(v, wv.y, acc.y);
        acc.z = fmaf(v, wv.z, acc.z);
        acc.w = fmaf(v, wv.w, acc.w);
    }
    #pragma unroll
    for (int off = 16; off; off >>= 1) {
        acc.x += __shfl_xor_sync(~0u, acc.x, off);
        acc.y += __shfl_xor_sync(~0u, acc.y, off);
        acc.z += __shfl_xor_sync(~0u, acc.z, off);
        acc.w += __shfl_xor_sync(~0u, acc.w, off);
    }
    __shared__ float4 red[8];
    if ((tid & 31) == 0) red[tid >> 5] = acc;
    __syncthreads();
    if (tid == 0) {
        float4 a = red[0];
        #pragma unroll
        for (int i = 1; i < 8; i++) {
            a.x += red[i].x; a.y += red[i].y; a.z += red[i].z; a.w += red[i].w;
        }
        float l0 = a.x + bg[0], l1 = a.y + bg[1], l2 = a.z + bg[2], l3 = a.w + bg[3];
        float mx = fmaxf(fmaxf(l0, l1), fmaxf(l2, l3));
        float e0 = __expf(l0 - mx), e1 = __expf(l1 - mx),
              e2 = __expf(l2 - mx), e3 = __expf(l3 - mx);
        float inv = 1.f / (e0 + e1 + e2 + e3);
        gate[t * 4 + 0] = e0 * inv; gate[t * 4 + 1] = e1 * inv;
        gate[t * 4 + 2] = e2 * inv; gate[t * 4 + 3] = e3 * inv;
    }
}

__global__ void fusemix_k(const float* __restrict__ Ob,
                          const float* __restrict__ gate,
                          float* __restrict__ out) {
    int idx = blockIdx.x * 256 + threadIdx.x;
    int t = idx >> 10;
    float g0 = gate[t * 4 + 0], g1 = gate[t * 4 + 1];
    float g2 = gate[t * 4 + 2], g3 = gate[t * 4 + 3];
    const size_t P = (size_t)TOK * Dc;
    out[idx] = g0 * Ob[idx] + g1 * Ob[idx + P] + g2 * Ob[idx + 2 * P] + g3 * Ob[idx + 3 * P];
}

__global__ void swiglu_k(const float* __restrict__ h1,
                         const float* __restrict__ h3,
                         float* __restrict__ out, size_t n) {
    size_t i = (size_t)blockIdx.x * 256 + threadIdx.x;
    if (i < n) {
        float a = h1[i];
        out[i] = (a / (1.f + __expf(-a))) * h3[i];
    }
}

// ---------------- host launch ----------------
extern "C" void kernel_launch(void* const* d_in, const int* in_sizes, int n_in,
                              void* d_out, int out_size) {
    const float* x      = (const float*)d_in[0];
    const float* t_emb  = (const float*)d_in[1];
    const float* ln1_g  = (const float*)d_in[2];
    const float* ln1_b  = (const float*)d_in[3];
    const float* ln2_g  = (const float*)d_in[4];
    const float* ln2_b  = (const float*)d_in[5];
    const float* ada_w  = (const float*)d_in[6];
    const float* ada_b  = (const float*)d_in[7];

    const float *fus_wg, *fus_bg, *fus_wo, *ffn_w1, *ffn_w2, *ffn_w3;
    int ab;
    if (in_sizes[8] == 16384) {
        fus_wg = (const float*)d_in[8];  fus_bg = (const float*)d_in[9];
        fus_wo = (const float*)d_in[10];
        ffn_w1 = (const float*)d_in[11]; ffn_w2 = (const float*)d_in[12];
        ffn_w3 = (const float*)d_in[13];
        ab = 14;
    } else {
        ab = 8;
        fus_wg = (const float*)d_in[24]; fus_bg = (const float*)d_in[25];
        fus_wo = (const float*)d_in[26];
        ffn_w1 = (const float*)d_in[27]; ffn_w2 = (const float*)d_in[28];
        ffn_w3 = (const float*)d_in[29];
    }

    float *st, *ada, *nx, *q, *k, *v, *ao, *obr, *gate, *fused, *xmid, *h1, *h3;
    cudaGetSymbolAddress((void**)&st,    g_st);
    cudaGetSymbolAddress((void**)&ada,   g_ada);
    cudaGetSymbolAddress((void**)&nx,    g_nx);
    cudaGetSymbolAddress((void**)&q,     g_q);
    cudaGetSymbolAddress((void**)&k,     g_k);
    cudaGetSymbolAddress((void**)&v,     g_v);
    cudaGetSymbolAddress((void**)&ao,    g_ao);
    cudaGetSymbolAddress((void**)&obr,   g_obr);
    cudaGetSymbolAddress((void**)&gate,  g_gate);
    cudaGetSymbolAddress((void**)&fused, g_fused);
    cudaGetSymbolAddress((void**)&xmid,  g_xmid);
    cudaGetSymbolAddress((void**)&h1,    g_h1);
    cudaGetSymbolAddress((void**)&h3,    g_h3);

    float* out = (float*)d_out;

    // 1. AdaLN parameters
    silu_k<<<(Bc * Dc + 255) / 256, 256>>>(t_emb, st, Bc * Dc);
    ada_k<<<(Bc * SIXD) / 8, 256>>>(st, ada_w, ada_b, ada);

    // 2. nx = modulated LN(x)
    ln_mod_k<<<TOK, 256>>>(x, ln1_g, ln1_b, ada, 0, Dc, nx);

    // 3. four attention branches
    dim3 gProj(Dc / 128, TOK / 128);   // (8,32)
    dim3 gAttn(Sc / 8, Bc * Hc);       // (128,64)
    dim3 gSparse(Sc / 4, Bc * Hc);     // (256,64)
    for (int p = 0; p < 4; p++) {
        const float* wq = (const float*)d_in[ab + p * 4 + 0];
        const float* wk = (const float*)d_in[ab + p * 4 + 1];
        const float* wv = (const float*)d_in[ab + p * 4 + 2];
        const float* wo = (const float*)d_in[ab + p * 4 + 3];
        gemm_tc<<<gProj, 256>>>(nx, wq, q, TOK, Dc, Dc, nullptr, nullptr);
        gemm_tc<<<gProj, 256>>>(nx, wk, k, TOK, Dc, Dc, nullptr, nullptr);
        gemm_tc<<<gProj, 256>>>(nx, wv, v, TOK, Dc, Dc, nullptr, nullptr);
        if (p == 1 || p == 2) {
            attn_sparse_k<<<gSparse, 128>>>(q, k, v, ao, p);
        } else {
            attn_k<<<gAttn, 256>>>(q, k, v, ao, p);
        }
        gemm_tc<<<gProj, 256>>>(ao, wo, obr + (size_t)p * TOK * Dc, TOK, Dc, Dc,
                                nullptr, nullptr);
    }

    // 4. learned fusion + first residual (g_m at 2D)
    gate_k<<<TOK, 256>>>(obr, fus_wg, fus_bg, gate);
    fusemix_k<<<(TOK * Dc) / 256, 256>>>(obr, gate, fused);
    gemm_tc<<<gProj, 256>>>(fused, fus_wo, xmid, TOK, Dc, Dc, x, ada + 2 * Dc);

    // 5. FFN with AdaLN (sh_f at 3D, sc_f at 4D, g_f at 5D)
    ln_mod_k<<<TOK, 256>>>(xmid, ln2_g, ln2_b, ada, 3 * Dc, 4 * Dc, nx);
    dim3 gFfnUp(Fc / 128, TOK / 128);    // (32,32)
    gemm_tc<<<gFfnUp, 256>>>(nx, ffn_w1, h1, TOK, Fc, Dc, nullptr, nullptr);
    gemm_tc<<<gFfnUp, 256>>>(nx, ffn_w3, h3, TOK, Fc, Dc, nullptr, nullptr);
    size_t nf = (size_t)TOK * Fc;
    swiglu_k<<<(unsigned)((nf + 255) / 256), 256>>>(h1, h3, h1, nf);
    gemm_tc<<<gProj, 256>>>(h1, ffn_w2, out, TOK, Dc, Fc, xmid, ada + 5 * Dc);
}

// round 3
// speedup vs baseline: 5.0837x; 2.3743x over previous
#include <cuda_runtime.h>
#include <math.h>
#include <stdint.h>

// Problem constants
#define Bc   4
#define Sc   1024
#define Dc   1024
#define Hc   16
#define DHc  64
#define Fc   4096
#define TOK  4096          // B*S
#define SIXD 6144          // 6*D

// ---------------- scratch (no allocations allowed) ----------------
__device__ float g_st[Bc * Dc];
__device__ float g_ada[Bc * SIXD];
__device__ float g_nx[TOK * Dc];
__device__ float g_q[TOK * Dc];
__device__ float g_k[TOK * Dc];
__device__ float g_v[TOK * Dc];
__device__ float g_ao[TOK * Dc];
__device__ float g_obr[4 * TOK * Dc];
__device__ float g_gate[TOK * 4];
__device__ float g_fused[TOK * Dc];
__device__ float g_xmid[TOK * Dc];
__device__ float g_h1[TOK * Fc];
__device__ float g_h3[TOK * Fc];

// ---------------- ptx helpers ----------------
__device__ __forceinline__ float to_tf32(float x) {
    float r;
    asm("cvt.rna.tf32.f32 %0, %1;" : "=f"(r) : "f"(x));
    return r;
}
__device__ __forceinline__ uint32_t tf32u(float x) {
    return __float_as_uint(to_tf32(x));
}
__device__ __forceinline__ void mma_tf32(float* c, uint32_t a0, uint32_t a1,
                                         uint32_t a2, uint32_t a3,
                                         uint32_t b0, uint32_t b1) {
    asm("mma.sync.aligned.m16n8k8.row.col.f32.tf32.tf32.f32 "
        "{%0,%1,%2,%3},{%4,%5,%6,%7},{%8,%9},{%0,%1,%2,%3};"
        : "+f"(c[0]), "+f"(c[1]), "+f"(c[2]), "+f"(c[3])
        : "r"(a0), "r"(a1), "r"(a2), "r"(a3), "r"(b0), "r"(b1));
}
__device__ __forceinline__ void cp16(void* smem, const void* g) {
    uint32_t s = (uint32_t)__cvta_generic_to_shared(smem);
    asm volatile("cp.async.cg.shared.global [%0], [%1], 16;" :: "r"(s), "l"(g));
}
__device__ __forceinline__ void cp_commit() {
    asm volatile("cp.async.commit_group;");
}
template <int N>
__device__ __forceinline__ void cp_wait() {
    asm volatile("cp.async.wait_group %0;" :: "n"(N));
}

// ---------------- elementwise helpers ----------------
__global__ void silu_k(const float* __restrict__ in, float* __restrict__ out, int n) {
    int i = blockIdx.x * blockDim.x + threadIdx.x;
    if (i < n) { float v = in[i]; out[i] = v / (1.f + __expf(-v)); }
}

__global__ __launch_bounds__(256) void ada_k(const float* __restrict__ st,
                                             const float* __restrict__ W,
                                             const float* __restrict__ bias,
                                             float* __restrict__ out) {
    int o = blockIdx.x * 8 + (threadIdx.x >> 5);
    int lane = threadIdx.x & 31;
    int b = o / SIXD, n = o - b * SIXD;
    float acc = 0.f;
    for (int k = lane; k < Dc; k += 32)
        acc = fmaf(st[b * Dc + k], W[(size_t)k * SIXD + n], acc);
    #pragma unroll
    for (int off = 16; off; off >>= 1) acc += __shfl_xor_sync(~0u, acc, off);
    if (!lane) out[o] = acc + bias[n];
}

__global__ __launch_bounds__(256) void ln_mod_k(const float* __restrict__ X,
                                                const float* __restrict__ gam,
                                                const float* __restrict__ bet,
                                                const float* __restrict__ ada,
                                                int sh_off, int sc_off,
                                                float* __restrict__ out) {
    int t = blockIdx.x;
    int b = t >> 10;
    int tid = threadIdx.x;
    const float* xr = X + (size_t)t * Dc;
    float s = 0.f, ss = 0.f;
    for (int i = tid; i < Dc; i += 256) { float v = xr[i]; s += v; ss = fmaf(v, v, ss); }
    __shared__ float r1[8], r2[8];
    __shared__ float muS, rsS;
    #pragma unroll
    for (int off = 16; off; off >>= 1) {
        s  += __shfl_xor_sync(~0u, s,  off);
        ss += __shfl_xor_sync(~0u, ss, off);
    }
    if ((tid & 31) == 0) { r1[tid >> 5] = s; r2[tid >> 5] = ss; }
    __syncthreads();
    if (tid < 32) {
        float a = (tid < 8) ? r1[tid] : 0.f;
        float c = (tid < 8) ? r2[tid] : 0.f;
        #pragma unroll
        for (int off = 4; off; off >>= 1) {
            a += __shfl_xor_sync(~0u, a, off);
            c += __shfl_xor_sync(~0u, c, off);
        }
        if (tid == 0) {
            float mu = a * (1.f / Dc);
            float var = c * (1.f / Dc) - mu * mu;
            muS = mu; rsS = rsqrtf(var + 1e-6f);
        }
    }
    __syncthreads();
    float mu = muS, rs = rsS;
    const float* ar = ada + b * SIXD;
    float* orow = out + (size_t)t * Dc;
    for (int i = tid; i < Dc; i += 256) {
        float v = (xr[i] - mu) * rs * gam[i] + bet[i];
        orow[i] = fmaf(v, 1.f + ar[sc_off + i], ar[sh_off + i]);
    }
}

// ---------------- TF32 TC GEMM, cp.async double-buffered ----------------
// C = A[M,K] @ B[K,N]; 128x128 tile, 8 warps of 64x32.
// resid != nullptr: C[t,n] = resid[t,n] + gate[(t>>10)*SIXD + n] * acc
#define AP 20
#define BP 136

__global__ __launch_bounds__(256) void gemm_tc(const float* __restrict__ A,
                                               const float* __restrict__ B,
                                               float* __restrict__ C,
                                               int M, int N, int K,
                                               const float* __restrict__ resid,
                                               const float* __restrict__ gate) {
    __shared__ float As[2][128][AP];   // [m][k], pad 20 -> conflict-free frag gathers
    __shared__ float Bs[2][16][BP];    // [k][n], pad 136
    int tid = threadIdx.x;
    int bx = blockIdx.x, by = blockIdx.y;
    int w = tid >> 5, lane = tid & 31;
    int wm = (w >> 2) * 64, wn = (w & 3) * 32;
    int g = lane >> 2, t = lane & 3;

    float acc[4][4][4];
    #pragma unroll
    for (int i = 0; i < 4; i++)
        #pragma unroll
        for (int j = 0; j < 4; j++)
            #pragma unroll
            for (int r = 0; r < 4; r++) acc[i][j][r] = 0.f;

    const float* Ag = A + (size_t)(by * 128) * K;
    const float* Bg = B + bx * 128;

    // cp.async loaders: 512 16B segs each for A and B, 2 per thread per matrix
    int sA0 = tid, sA1 = tid + 256;
    int arow0 = sA0 >> 2, ac0 = (sA0 & 3) << 2;
    int arow1 = sA1 >> 2, ac1 = (sA1 & 3) << 2;
    int brow0 = sA0 >> 5, bc0 = (sA0 & 31) << 2;
    int brow1 = sA1 >> 5, bc1 = (sA1 & 31) << 2;

    auto load_stage = [&](int st, int k0) {
        cp16(&As[st][arow0][ac0], Ag + (size_t)arow0 * K + k0 + ac0);
        cp16(&As[st][arow1][ac1], Ag + (size_t)arow1 * K + k0 + ac1);
        cp16(&Bs[st][brow0][bc0], Bg + (size_t)(k0 + brow0) * N + bc0);
        cp16(&Bs[st][brow1][bc1], Bg + (size_t)(k0 + brow1) * N + bc1);
    };

    load_stage(0, 0);
    cp_commit();
    int cur = 0;

    for (int k0 = 0; k0 < K; k0 += 16) {
        if (k0 + 16 < K) {
            load_stage(cur ^ 1, k0 + 16);
            cp_commit();
            cp_wait<1>();
        } else {
            cp_wait<0>();
        }
        __syncthreads();

        #pragma unroll
        for (int ks = 0; ks < 16; ks += 8) {
            uint32_t af[4][4], bf[4][2];
            int kLo = ks + t, kHi = ks + t + 4;
            #pragma unroll
            for (int i = 0; i < 4; i++) {
                int m0 = wm + 16 * i + g;
                af[i][0] = tf32u(As[cur][m0][kLo]);
                af[i][1] = tf32u(As[cur][m0 + 8][kLo]);
                af[i][2] = tf32u(As[cur][m0][kHi]);
                af[i][3] = tf32u(As[cur][m0 + 8][kHi]);
            }
            #pragma unroll
            for (int j = 0; j < 4; j++) {
                int n0 = wn + 8 * j + g;
                bf[j][0] = tf32u(Bs[cur][kLo][n0]);
                bf[j][1] = tf32u(Bs[cur][kHi][n0]);
            }
            #pragma unroll
            for (int i = 0; i < 4; i++)
                #pragma unroll
                for (int j = 0; j < 4; j++)
                    mma_tf32(acc[i][j], af[i][0], af[i][1], af[i][2], af[i][3],
                             bf[j][0], bf[j][1]);
        }
        __syncthreads();
        cur ^= 1;
    }

    #pragma unroll
    for (int i = 0; i < 4; i++) {
        #pragma unroll
        for (int j = 0; j < 4; j++) {
            int row0 = by * 128 + wm + 16 * i + g;
            int col  = bx * 128 + wn + 8 * j + 2 * t;
            size_t b0i = (size_t)row0 * N + col;
            size_t b1i = (size_t)(row0 + 8) * N + col;
            if (resid == nullptr) {
                *(float2*)&C[b0i] = make_float2(acc[i][j][0], acc[i][j][1]);
                *(float2*)&C[b1i] = make_float2(acc[i][j][2], acc[i][j][3]);
            } else {
                int bb0 = row0 >> 10, bb1 = (row0 + 8) >> 10;
                float2 gr0 = *(const float2*)&gate[(size_t)bb0 * SIXD + col];
                float2 gr1 = *(const float2*)&gate[(size_t)bb1 * SIXD + col];
                float2 r0 = *(const float2*)&resid[b0i];
                float2 r1 = *(const float2*)&resid[b1i];
                *(float2*)&C[b0i] = make_float2(fmaf(gr0.x, acc[i][j][0], r0.x),
                                                fmaf(gr0.y, acc[i][j][1], r0.y));
                *(float2*)&C[b1i] = make_float2(fmaf(gr1.x, acc[i][j][2], r1.x),
                                                fmaf(gr1.y, acc[i][j][3], r1.y));
            }
        }
    }
}

// ---------------- tensor-core flash attention (full branches) ----------------
// 128 queries/CTA, 8 warps x 16 rows, 64-key tiles, m16n8k8 tf32.
// branch 0: bias = -|qi-kj|; branch 3: no bias.
// dyn smem: Ps[128][68] (Q stage, then P) | Ks[64][68] | Vs[64][72]
#define ATT_PS   0
#define ATT_KS   8704
#define ATT_VS   13056
#define ATT_SMEM_BYTES ((8704 + 4352 + 4608) * 4)

__global__ __launch_bounds__(256) void attn_tc_k(const float* __restrict__ Q,
                                                 const float* __restrict__ Km,
                                                 const float* __restrict__ Vm,
                                                 float* __restrict__ O, int branch) {
    extern __shared__ float sm[];
    float* Ps = sm + ATT_PS;
    float* Ks = sm + ATT_KS;
    float* Vs = sm + ATT_VS;
    int tid = threadIdx.x, lane = tid & 31, w = tid >> 5;
    int g = lane >> 2, t = lane & 3;
    int bh = blockIdx.y;
    int b = bh >> 4, h = bh & 15;
    int qb = blockIdx.x * 128;
    int headoff = h * DHc;

    // stage Q (with tf32 cvt)
    #pragma unroll
    for (int i = 0; i < 8; i++) {
        int seg = tid + i * 256;
        int row = seg >> 4, c4 = (seg & 15) << 2;
        float4 v = *(const float4*)&Q[((size_t)(b * Sc + qb + row)) * Dc + headoff + c4];
        float4 cv = make_float4(to_tf32(v.x), to_tf32(v.y), to_tf32(v.z), to_tf32(v.w));
        *(float4*)&Ps[row * 68 + c4] = cv;
    }
    __syncthreads();

    // preload Q fragments (then Ps is reused as P buffer, per-warp private rows)
    int r0 = w * 16 + g;
    uint32_t qa[8][4];
    #pragma unroll
    for (int kk = 0; kk < 8; kk++) {
        qa[kk][0] = __float_as_uint(Ps[r0 * 68 + kk * 8 + t]);
        qa[kk][1] = __float_as_uint(Ps[(r0 + 8) * 68 + kk * 8 + t]);
        qa[kk][2] = __float_as_uint(Ps[r0 * 68 + kk * 8 + t + 4]);
        qa[kk][3] = __float_as_uint(Ps[(r0 + 8) * 68 + kk * 8 + t + 4]);
    }

    float m0 = -INFINITY, m1 = -INFINITY, l0 = 0.f, l1 = 0.f;
    float o[8][4];
    #pragma unroll
    for (int j = 0; j < 8; j++)
        #pragma unroll
        for (int r = 0; r < 4; r++) o[j][r] = 0.f;

    int qi0 = qb + r0, qi1 = qi0 + 8;

    for (int kt = 0; kt < Sc; kt += 64) {
        __syncthreads();   // previous tile's reads done before overwrite
        #pragma unroll
        for (int i = 0; i < 4; i++) {
            int seg = tid + i * 256;
            int row = seg >> 4, c4 = (seg & 15) << 2;
            size_t gi = ((size_t)(b * Sc + kt + row)) * Dc + headoff + c4;
            float4 kv = *(const float4*)&Km[gi];
            float4 vv = *(const float4*)&Vm[gi];
            *(float4*)&Ks[row * 68 + c4] =
                make_float4(to_tf32(kv.x), to_tf32(kv.y), to_tf32(kv.z), to_tf32(kv.w));
            *(float4*)&Vs[row * 72 + c4] =
                make_float4(to_tf32(vv.x), to_tf32(vv.y), to_tf32(vv.z), to_tf32(vv.w));
        }
        __syncthreads();

        // scores: 16x64 per warp
        float sc[8][4];
        #pragma unroll
        for (int jn = 0; jn < 8; jn++)
            #pragma unroll
            for (int r = 0; r < 4; r++) sc[jn][r] = 0.f;
        #pragma unroll
        for (int kk = 0; kk < 8; kk++) {
            #pragma unroll
            for (int jn = 0; jn < 8; jn++) {
                uint32_t b0 = __float_as_uint(Ks[(jn * 8 + g) * 68 + kk * 8 + t]);
                uint32_t b1 = __float_as_uint(Ks[(jn * 8 + g) * 68 + kk * 8 + t + 4]);
                mma_tf32(sc[jn], qa[kk][0], qa[kk][1], qa[kk][2], qa[kk][3], b0, b1);
            }
        }

        // scale + bias, online softmax
        float rm0 = m0, rm1 = m1;
        #pragma unroll
        for (int jn = 0; jn < 8; jn++) {
            int kj = kt + jn * 8 + 2 * t;
            float b00 = 0.f, b01 = 0.f, b10 = 0.f, b11 = 0.f;
            if (branch == 0) {
                b00 = -(float)abs(qi0 - kj);     b01 = -(float)abs(qi0 - kj - 1);
                b10 = -(float)abs(qi1 - kj);     b11 = -(float)abs(qi1 - kj - 1);
            }
            sc[jn][0] = fmaf(sc[jn][0], 0.125f, b00);
            sc[jn][1] = fmaf(sc[jn][1], 0.125f, b01);
            sc[jn][2] = fmaf(sc[jn][2], 0.125f, b10);
            sc[jn][3] = fmaf(sc[jn][3], 0.125f, b11);
            rm0 = fmaxf(rm0, fmaxf(sc[jn][0], sc[jn][1]));
            rm1 = fmaxf(rm1, fmaxf(sc[jn][2], sc[jn][3]));
        }
        rm0 = fmaxf(rm0, __shfl_xor_sync(~0u, rm0, 1));
        rm0 = fmaxf(rm0, __shfl_xor_sync(~0u, rm0, 2));
        rm1 = fmaxf(rm1, __shfl_xor_sync(~0u, rm1, 1));
        rm1 = fmaxf(rm1, __shfl_xor_sync(~0u, rm1, 2));
        float corr0 = __expf(m0 - rm0), corr1 = __expf(m1 - rm1);
        m0 = rm0; m1 = rm1;

        float sum0 = 0.f, sum1 = 0.f;
        #pragma unroll
        for (int jn = 0; jn < 8; jn++) {
            float p0 = __expf(sc[jn][0] - m0), p1 = __expf(sc[jn][1] - m0);
            float p2 = __expf(sc[jn][2] - m1), p3 = __expf(sc[jn][3] - m1);
            sum0 += p0 + p1; sum1 += p2 + p3;
            *(float2*)&Ps[r0 * 68 + jn * 8 + 2 * t] =
                make_float2(to_tf32(p0), to_tf32(p1));
            *(float2*)&Ps[(r0 + 8) * 68 + jn * 8 + 2 * t] =
                make_float2(to_tf32(p2), to_tf32(p3));
        }
        sum0 += __shfl_xor_sync(~0u, sum0, 1);
        sum0 += __shfl_xor_sync(~0u, sum0, 2);
        sum1 += __shfl_xor_sync(~0u, sum1, 1);
        sum1 += __shfl_xor_sync(~0u, sum1, 2);
        l0 = fmaf(l0, corr0, sum0);
        l1 = fmaf(l1, corr1, sum1);
        #pragma unroll
        for (int jd = 0; jd < 8; jd++) {
            o[jd][0] *= corr0; o[jd][1] *= corr0;
            o[jd][2] *= corr1; o[jd][3] *= corr1;
        }
        __syncwarp();  // P rows are warp-private; warp-local ordering suffices

        // PV: 16x64 += P(16x64) @ V(64x64)
        #pragma unroll
        for (int ks = 0; ks < 8; ks++) {
            uint32_t pa0 = __float_as_uint(Ps[r0 * 68 + ks * 8 + t]);
            uint32_t pa1 = __float_as_uint(Ps[(r0 + 8) * 68 + ks * 8 + t]);
            uint32_t pa2 = __float_as_uint(Ps[r0 * 68 + ks * 8 + t + 4]);
            uint32_t pa3 = __float_as_uint(Ps[(r0 + 8) * 68 + ks * 8 + t + 4]);
            #pragma unroll
            for (int jd = 0; jd < 8; jd++) {
                uint32_t vb0 = __float_as_uint(Vs[(ks * 8 + t) * 72 + jd * 8 + g]);
                uint32_t vb1 = __float_as_uint(Vs[(ks * 8 + t + 4) * 72 + jd * 8 + g]);
                mma_tf32(o[jd], pa0, pa1, pa2, pa3, vb0, vb1);
            }
        }
    }

    float inv0 = 1.f / l0, inv1 = 1.f / l1;
    size_t row0g = ((size_t)(b * Sc + qb + r0)) * Dc + headoff;
    size_t row1g = row0g + (size_t)8 * Dc;
    #pragma unroll
    for (int jd = 0; jd < 8; jd++) {
        int col = jd * 8 + 2 * t;
        *(float2*)&O[row0g + col] = make_float2(o[jd][0] * inv0, o[jd][1] * inv0);
        *(float2*)&O[row1g + col] = make_float2(o[jd][2] * inv1, o[jd][3] * inv1);
    }
}

// ---------------- sparse attention for masked branches ----------------
__global__ __launch_bounds__(128) void attn_sparse_k(const float* __restrict__ Q,
                                                     const float* __restrict__ Km,
                                                     const float* __restrict__ Vm,
                                                     float* __restrict__ O, int mode) {
    int w = threadIdx.x >> 5, lane = threadIdx.x & 31;
    int qi = blockIdx.x * 4 + w;
    int bh = blockIdx.y;
    int b = bh >> 4, h = bh & 15;
    size_t rowbase = ((size_t)(b * Sc + qi)) * Dc + (size_t)h * DHc;
    float q0 = Q[rowbase + lane], q1 = Q[rowbase + 32 + lane];

    int k0i, nk;
    if (mode == 1) {
        k0i = qi - 1; nk = 3;
        if (qi == 0)      { k0i = 0; nk = 2; }
        if (qi == Sc - 1) { nk = 2; }
    } else {
        k0i = qi & ~1; nk = 2;
    }

    float s[3] = {0.f, 0.f, 0.f};
    #pragma unroll 3
    for (int kk = 0; kk < 3; kk++) {
        if (kk < nk) {
            size_t kb = ((size_t)(b * Sc + k0i + kk)) * Dc + (size_t)h * DHc;
            float acc = fmaf(q0, Km[kb + lane], q1 * Km[kb + 32 + lane]);
            #pragma unroll
            for (int off = 16; off; off >>= 1)
                acc += __shfl_xor_sync(~0u, acc, off);
            s[kk] = acc * 0.125f;
        }
    }
    float mx = s[0];
    for (int kk = 1; kk < nk; kk++) mx = fmaxf(mx, s[kk]);
    float p[3], l = 0.f;
    for (int kk = 0; kk < nk; kk++) { p[kk] = __expf(s[kk] - mx); l += p[kk]; }
    float inv = 1.f / l;

    float o0 = 0.f, o1 = 0.f;
    #pragma unroll 3
    for (int kk = 0; kk < 3; kk++) {
        if (kk < nk) {
            size_t vb = ((size_t)(b * Sc + k0i + kk)) * Dc + (size_t)h * DHc;
            o0 = fmaf(p[kk], Vm[vb + lane], o0);
            o1 = fmaf(p[kk], Vm[vb + 32 + lane], o1);
        }
    }
    O[rowbase + lane]      = o0 * inv;
    O[rowbase + 32 + lane] = o1 * inv;
}

// ---------------- fusion gate ----------------
__global__ __launch_bounds__(256) void gate_k(const float* __restrict__ Ob,
                                              const float* __restrict__ wg,
                                              const float* __restrict__ bg,
                                              float* __restrict__ gate) {
    int t = blockIdx.x, tid = threadIdx.x;
    float4 acc = make_float4(0.f, 0.f, 0.f, 0.f);
    for (int d = tid; d < 4 * Dc; d += 256) {
        int p = d >> 10, dd = d & 1023;
        float v = Ob[((size_t)p * TOK + t) * Dc + dd];
        float4 wv = *(const float4*)&wg[(size_t)d * 4];
        acc.x = fmaf(v, wv.x, acc.x);
        acc.y = fmaf(v, wv.y, acc.y);
        acc.z = fmaf(v, wv.z, acc.z);
        acc.w = fmaf(v, wv.w, acc.w);
    }
    #pragma unroll
    for (int off = 16; off; off >>= 1) {
        acc.x += __shfl_xor_sync(~0u, acc.x, off);
        acc.y += __shfl_xor_sync(~0u, acc.y, off);
        acc.z += __shfl_xor_sync(~0u, acc.z, off);
        acc.w += __shfl_xor_sync(~0u, acc.w, off);
    }
    __shared__ float4 red[8];
    if ((tid & 31) == 0) red[tid >> 5] = acc;
    __syncthreads();
    if (tid == 0) {
        float4 a = red[0];
        #pragma unroll
        for (int i = 1; i < 8; i++) {
            a.x += red[i].x; a.y += red[i].y; a.z += red[i].z; a.w += red[i].w;
        }
        float l0 = a.x + bg[0], l1 = a.y + bg[1], l2 = a.z + bg[2], l3 = a.w + bg[3];
        float mx = fmaxf(fmaxf(l0, l1), fmaxf(l2, l3));
        float e0 = __expf(l0 - mx), e1 = __expf(l1 - mx),
              e2 = __expf(l2 - mx), e3 = __expf(l3 - mx);
        float inv = 1.f / (e0 + e1 + e2 + e3);
        gate[t * 4 + 0] = e0 * inv; gate[t * 4 + 1] = e1 * inv;
        gate[t * 4 + 2] = e2 * inv; gate[t * 4 + 3] = e3 * inv;
    }
}

__global__ void fusemix_k(const float* __restrict__ Ob,
                          const float* __restrict__ gate,
                          float* __restrict__ out) {
    int idx = blockIdx.x * 256 + threadIdx.x;
    int t = idx >> 10;
    float g0 = gate[t * 4 + 0], g1 = gate[t * 4 + 1];
    float g2 = gate[t * 4 + 2], g3 = gate[t * 4 + 3];
    const size_t P = (size_t)TOK * Dc;
    out[idx] = g0 * Ob[idx] + g1 * Ob[idx + P] + g2 * Ob[idx + 2 * P] + g3 * Ob[idx + 3 * P];
}

__global__ void swiglu_k(const float* __restrict__ h1,
                         const float* __restrict__ h3,
                         float* __restrict__ out, size_t n) {
    size_t i = (size_t)blockIdx.x * 256 + threadIdx.x;
    if (i < n) {
        float a = h1[i];
        out[i] = (a / (1.f + __expf(-a))) * h3[i];
    }
}

// ---------------- host launch ----------------
extern "C" void kernel_launch(void* const* d_in, const int* in_sizes, int n_in,
                              void* d_out, int out_size) {
    const float* x      = (const float*)d_in[0];
    const float* t_emb  = (const float*)d_in[1];
    const float* ln1_g  = (const float*)d_in[2];
    const float* ln1_b  = (const float*)d_in[3];
    const float* ln2_g  = (const float*)d_in[4];
    const float* ln2_b  = (const float*)d_in[5];
    const float* ada_w  = (const float*)d_in[6];
    const float* ada_b  = (const float*)d_in[7];

    const float *fus_wg, *fus_bg, *fus_wo, *ffn_w1, *ffn_w2, *ffn_w3;
    int ab;
    if (in_sizes[8] == 16384) {
        fus_wg = (const float*)d_in[8];  fus_bg = (const float*)d_in[9];
        fus_wo = (const float*)d_in[10];
        ffn_w1 = (const float*)d_in[11]; ffn_w2 = (const float*)d_in[12];
        ffn_w3 = (const float*)d_in[13];
        ab = 14;
    } else {
        ab = 8;
        fus_wg = (const float*)d_in[24]; fus_bg = (const float*)d_in[25];
        fus_wo = (const float*)d_in[26];
        ffn_w1 = (const float*)d_in[27]; ffn_w2 = (const float*)d_in[28];
        ffn_w3 = (const float*)d_in[29];
    }

    float *st, *ada, *nx, *q, *k, *v, *ao, *obr, *gate, *fused, *xmid, *h1, *h3;
    cudaGetSymbolAddress((void**)&st,    g_st);
    cudaGetSymbolAddress((void**)&ada,   g_ada);
    cudaGetSymbolAddress((void**)&nx,    g_nx);
    cudaGetSymbolAddress((void**)&q,     g_q);
    cudaGetSymbolAddress((void**)&k,     g_k);
    cudaGetSymbolAddress((void**)&v,     g_v);
    cudaGetSymbolAddress((void**)&ao,    g_ao);
    cudaGetSymbolAddress((void**)&obr,   g_obr);
    cudaGetSymbolAddress((void**)&gate,  g_gate);
    cudaGetSymbolAddress((void**)&fused, g_fused);
    cudaGetSymbolAddress((void**)&xmid,  g_xmid);
    cudaGetSymbolAddress((void**)&h1,    g_h1);
    cudaGetSymbolAddress((void**)&h3,    g_h3);

    cudaFuncSetAttribute(attn_tc_k, cudaFuncAttributeMaxDynamicSharedMemorySize,
                         ATT_SMEM_BYTES);

    float* out = (float*)d_out;

    // 1. AdaLN parameters
    silu_k<<<(Bc * Dc + 255) / 256, 256>>>(t_emb, st, Bc * Dc);
    ada_k<<<(Bc * SIXD) / 8, 256>>>(st, ada_w, ada_b, ada);

    // 2. nx = modulated LN(x)
    ln_mod_k<<<TOK, 256>>>(x, ln1_g, ln1_b, ada, 0, Dc, nx);

    // 3. four attention branches
    dim3 gProj(Dc / 128, TOK / 128);   // (8,32)
    dim3 gAttn(Sc / 128, Bc * Hc);     // (8,64)
    dim3 gSparse(Sc / 4, Bc * Hc);     // (256,64)
    for (int p = 0; p < 4; p++) {
        const float* wq = (const float*)d_in[ab + p * 4 + 0];
        const float* wk = (const float*)d_in[ab + p * 4 + 1];
        const float* wv = (const float*)d_in[ab + p * 4 + 2];
        const float* wo = (const float*)d_in[ab + p * 4 + 3];
        gemm_tc<<<gProj, 256>>>(nx, wq, q, TOK, Dc, Dc, nullptr, nullptr);
        gemm_tc<<<gProj, 256>>>(nx, wk, k, TOK, Dc, Dc, nullptr, nullptr);
        gemm_tc<<<gProj, 256>>>(nx, wv, v, TOK, Dc, Dc, nullptr, nullptr);
        if (p == 1 || p == 2) {
            attn_sparse_k<<<gSparse, 128>>>(q, k, v, ao, p);
        } else {
            attn_tc_k<<<gAttn, 256, ATT_SMEM_BYTES>>>(q, k, v, ao, p);
        }
        gemm_tc<<<gProj, 256>>>(ao, wo, obr + (size_t)p * TOK * Dc, TOK, Dc, Dc,
                                nullptr, nullptr);
    }

    // 4. learned fusion + first residual (g_m at 2D)
    gate_k<<<TOK, 256>>>(obr, fus_wg, fus_bg, gate);
    fusemix_k<<<(TOK * Dc) / 256, 256>>>(obr, gate, fused);
    gemm_tc<<<gProj, 256>>>(fused, fus_wo, xmid, TOK, Dc, Dc, x, ada + 2 * Dc);

    // 5. FFN with AdaLN
    ln_mod_k<<<TOK, 256>>>(xmid, ln2_g, ln2_b, ada, 3 * Dc, 4 * Dc, nx);
    dim3 gFfnUp(Fc / 128, TOK / 128);    // (32,32)
    gemm_tc<<<gFfnUp, 256>>>(nx, ffn_w1, h1, TOK, Fc, Dc, nullptr, nullptr);
    gemm_tc<<<gFfnUp, 256>>>(nx, ffn_w3, h3, TOK, Fc, Dc, nullptr, nullptr);
    size_t nf = (size_t)TOK * Fc;
    swiglu_k<<<(unsigned)((nf + 255) / 256), 256>>>(h1, h3, h1, nf);
    gemm_tc<<<gProj, 256>>>(h1, ffn_w2, out, TOK, Dc, Fc, xmid, ada + 5 * Dc);
}

// round 4
// speedup vs baseline: 5.6660x; 1.1145x over previous
#include <cuda_runtime.h>
#include <math.h>
#include <stdint.h>

// Problem constants
#define Bc   4
#define Sc   1024
#define Dc   1024
#define Hc   16
#define DHc  64
#define Fc   4096
#define TOK  4096          // B*S
#define SIXD 6144          // 6*D
#define TOKD ((size_t)TOK * Dc)   // 4M
#define TOKF ((size_t)TOK * Fc)   // 16M

// ---------------- scratch (no allocations allowed) ----------------
__device__ float g_st[Bc * Dc];
__device__ float g_ada[Bc * SIXD];
__device__ float g_nx[TOK * Dc];
__device__ float g_w[(size_t)29 << 20];     // pre-rounded weights
__device__ float g_qkv[12 * TOK * Dc];      // q,k,v for 4 branches
__device__ float g_ao4[4 * TOK * Dc];       // attention outputs (pre-Wo)
__device__ float g_obr[4 * TOK * Dc];       // branch outputs
__device__ float g_gate[TOK * 4];
__device__ float g_fused[TOK * Dc];
__device__ float g_xmid[TOK * Dc];
__device__ float g_h[2 * TOK * Fc];         // h1, h3

// weight scratch offsets (floats)
#define WQKV 0
#define WO   ((size_t)12 << 20)
#define WFUS ((size_t)16 << 20)
#define W1   ((size_t)17 << 20)
#define W3   ((size_t)21 << 20)
#define W2   ((size_t)25 << 20)

// ---------------- ptx helpers ----------------
__device__ __forceinline__ float to_tf32(float x) {
    float r;
    asm("cvt.rna.tf32.f32 %0, %1;" : "=f"(r) : "f"(x));
    return r;
}
__device__ __forceinline__ void mma_tf32(float* c, uint32_t a0, uint32_t a1,
                                         uint32_t a2, uint32_t a3,
                                         uint32_t b0, uint32_t b1) {
    asm("mma.sync.aligned.m16n8k8.row.col.f32.tf32.tf32.f32 "
        "{%0,%1,%2,%3},{%4,%5,%6,%7},{%8,%9},{%0,%1,%2,%3};"
        : "+f"(c[0]), "+f"(c[1]), "+f"(c[2]), "+f"(c[3])
        : "r"(a0), "r"(a1), "r"(a2), "r"(a3), "r"(b0), "r"(b1));
}
__device__ __forceinline__ void cp16(void* smem, const void* g) {
    uint32_t s = (uint32_t)__cvta_generic_to_shared(smem);
    asm volatile("cp.async.cg.shared.global [%0], [%1], 16;" :: "r"(s), "l"(g));
}
__device__ __forceinline__ void cp_commit() {
    asm volatile("cp.async.commit_group;");
}
template <int N>
__device__ __forceinline__ void cp_wait() {
    asm volatile("cp.async.wait_group %0;" :: "n"(N));
}

// ---------------- weight pre-rounding ----------------
struct WPtrs { const float* p[20]; };

__global__ __launch_bounds__(256) void wround_k(WPtrs wp, float* __restrict__ dst) {
    size_t i4 = ((size_t)blockIdx.x * 256 + threadIdx.x) * 4;
    if (i4 >= ((size_t)29 << 20)) return;
    int r; size_t off;
    if (i4 < ((size_t)17 << 20)) { r = (int)(i4 >> 20); off = i4 & ((1u << 20) - 1); }
    else {
        size_t j = i4 - ((size_t)17 << 20);
        r = 17 + (int)(j >> 22); off = j & ((1u << 22) - 1);
    }
    float4 v = *(const float4*)(wp.p[r] + off);
    *(float4*)(dst + i4) = make_float4(to_tf32(v.x), to_tf32(v.y),
                                       to_tf32(v.z), to_tf32(v.w));
}

// ---------------- elementwise helpers ----------------
__global__ void silu_k(const float* __restrict__ in, float* __restrict__ out, int n) {
    int i = blockIdx.x * blockDim.x + threadIdx.x;
    if (i < n) { float v = in[i]; out[i] = v / (1.f + __expf(-v)); }
}

__global__ __launch_bounds__(256) void ada_k(const float* __restrict__ st,
                                             const float* __restrict__ W,
                                             const float* __restrict__ bias,
                                             float* __restrict__ out) {
    int o = blockIdx.x * 8 + (threadIdx.x >> 5);
    int lane = threadIdx.x & 31;
    int b = o / SIXD, n = o - b * SIXD;
    float acc = 0.f;
    for (int k = lane; k < Dc; k += 32)
        acc = fmaf(st[b * Dc + k], W[(size_t)k * SIXD + n], acc);
    #pragma unroll
    for (int off = 16; off; off >>= 1) acc += __shfl_xor_sync(~0u, acc, off);
    if (!lane) out[o] = acc + bias[n];
}

// nx = tf32( (LN(x)*g+b)*(1+sc)+sh )  (output pre-rounded for GEMM consumption)
__global__ __launch_bounds__(256) void ln_mod_k(const float* __restrict__ X,
                                                const float* __restrict__ gam,
                                                const float* __restrict__ bet,
                                                const float* __restrict__ ada,
                                                int sh_off, int sc_off,
                                                float* __restrict__ out) {
    int t = blockIdx.x;
    int b = t >> 10;
    int tid = threadIdx.x;
    const float* xr = X + (size_t)t * Dc;
    float s = 0.f, ss = 0.f;
    for (int i = tid; i < Dc; i += 256) { float v = xr[i]; s += v; ss = fmaf(v, v, ss); }
    __shared__ float r1[8], r2[8];
    __shared__ float muS, rsS;
    #pragma unroll
    for (int off = 16; off; off >>= 1) {
        s  += __shfl_xor_sync(~0u, s,  off);
        ss += __shfl_xor_sync(~0u, ss, off);
    }
    if ((tid & 31) == 0) { r1[tid >> 5] = s; r2[tid >> 5] = ss; }
    __syncthreads();
    if (tid < 32) {
        float a = (tid < 8) ? r1[tid] : 0.f;
        float c = (tid < 8) ? r2[tid] : 0.f;
        #pragma unroll
        for (int off = 4; off; off >>= 1) {
            a += __shfl_xor_sync(~0u, a, off);
            c += __shfl_xor_sync(~0u, c, off);
        }
        if (tid == 0) {
            float mu = a * (1.f / Dc);
            float var = c * (1.f / Dc) - mu * mu;
            muS = mu; rsS = rsqrtf(var + 1e-6f);
        }
    }
    __syncthreads();
    float mu = muS, rs = rsS;
    const float* ar = ada + b * SIXD;
    float* orow = out + (size_t)t * Dc;
    for (int i = tid; i < Dc; i += 256) {
        float v = (xr[i] - mu) * rs * gam[i] + bet[i];
        orow[i] = to_tf32(fmaf(v, 1.f + ar[sc_off + i], ar[sh_off + i]));
    }
}

// ---------------- TF32 TC GEMM, 3-stage cp.async, z-batched ----------------
// C = A[M,K] @ B[K,N]; 128x128 tile, 8 warps of 64x32.
// Inputs MUST be pre-rounded to tf32.
// resid != nullptr: C[t,n] = resid[t,n] + gate[(t>>10)*SIXD + n] * acc
#define AP 20
#define BP 136
#define GEMM_SMEM ((3 * (128 * AP) + 3 * (16 * BP)) * 4)   // 56832 B

__global__ __launch_bounds__(256, 2) void gemm_tc(
    const float* __restrict__ A, size_t azs,
    const float* __restrict__ B, size_t bzs,
    float* __restrict__ C, size_t czs,
    int M, int N, int K,
    const float* __restrict__ resid, const float* __restrict__ gate) {
    extern __shared__ float sm[];
    float* Asm = sm;                     // [3][128][AP]
    float* Bsm = sm + 3 * 128 * AP;      // [3][16][BP]
    #define ASI(st, m, k) Asm[(st) * (128 * AP) + (m) * AP + (k)]
    #define BSI(st, k, n) Bsm[(st) * (16 * BP) + (k) * BP + (n)]

    A += azs * blockIdx.z; B += bzs * blockIdx.z; C += czs * blockIdx.z;

    int tid = threadIdx.x;
    int bx = blockIdx.x, by = blockIdx.y;
    int w = tid >> 5, lane = tid & 31;
    int wm = (w >> 2) * 64, wn = (w & 3) * 32;
    int g = lane >> 2, t = lane & 3;

    float acc[4][4][4];
    #pragma unroll
    for (int i = 0; i < 4; i++)
        #pragma unroll
        for (int j = 0; j < 4; j++)
            #pragma unroll
            for (int r = 0; r < 4; r++) acc[i][j][r] = 0.f;

    const float* Ag = A + (size_t)(by * 128) * K;
    const float* Bg = B + bx * 128;

    int arow0 = tid >> 2, ac0 = (tid & 3) << 2;
    int arow1 = (tid + 256) >> 2, ac1 = ac0;   // tid+256: same col pattern
    int brow0 = tid >> 5, bc0 = (tid & 31) << 2;
    int brow1 = brow0 + 8, bc1 = bc0;

    auto load_stage = [&](int st, int k0) {
        cp16(&ASI(st, arow0, ac0), Ag + (size_t)arow0 * K + k0 + ac0);
        cp16(&ASI(st, arow1, ac1), Ag + (size_t)arow1 * K + k0 + ac1);
        cp16(&BSI(st, brow0, bc0), Bg + (size_t)(k0 + brow0) * N + bc0);
        cp16(&BSI(st, brow1, bc1), Bg + (size_t)(k0 + brow1) * N + bc1);
    };

    load_stage(0, 0);  cp_commit();
    load_stage(1, 16); cp_commit();
    int cur = 0;

    for (int k0 = 0; k0 < K; k0 += 16) {
        cp_wait<1>();
        __syncthreads();
        if (k0 + 32 < K) {
            int nst = cur + 2; if (nst >= 3) nst -= 3;
            load_stage(nst, k0 + 32);
        }
        cp_commit();

        #pragma unroll
        for (int ks = 0; ks < 16; ks += 8) {
            uint32_t af[4][4], bf[4][2];
            int kLo = ks + t, kHi = ks + t + 4;
            #pragma unroll
            for (int i = 0; i < 4; i++) {
                int m0 = wm + 16 * i + g;
                af[i][0] = __float_as_uint(ASI(cur, m0, kLo));
                af[i][1] = __float_as_uint(ASI(cur, m0 + 8, kLo));
                af[i][2] = __float_as_uint(ASI(cur, m0, kHi));
                af[i][3] = __float_as_uint(ASI(cur, m0 + 8, kHi));
            }
            #pragma unroll
            for (int j = 0; j < 4; j++) {
                int n0 = wn + 8 * j + g;
                bf[j][0] = __float_as_uint(BSI(cur, kLo, n0));
                bf[j][1] = __float_as_uint(BSI(cur, kHi, n0));
            }
            #pragma unroll
            for (int i = 0; i < 4; i++)
                #pragma unroll
                for (int j = 0; j < 4; j++)
                    mma_tf32(acc[i][j], af[i][0], af[i][1], af[i][2], af[i][3],
                             bf[j][0], bf[j][1]);
        }
        cur++; if (cur >= 3) cur -= 3;
    }

    #pragma unroll
    for (int i = 0; i < 4; i++) {
        #pragma unroll
        for (int j = 0; j < 4; j++) {
            int row0 = by * 128 + wm + 16 * i + g;
            int col  = bx * 128 + wn + 8 * j + 2 * t;
            size_t b0i = (size_t)row0 * N + col;
            size_t b1i = (size_t)(row0 + 8) * N + col;
            if (resid == nullptr) {
                *(float2*)&C[b0i] = make_float2(acc[i][j][0], acc[i][j][1]);
                *(float2*)&C[b1i] = make_float2(acc[i][j][2], acc[i][j][3]);
            } else {
                int bb0 = row0 >> 10, bb1 = (row0 + 8) >> 10;
                float2 gr0 = *(const float2*)&gate[(size_t)bb0 * SIXD + col];
                float2 gr1 = *(const float2*)&gate[(size_t)bb1 * SIXD + col];
                float2 r0 = *(const float2*)&resid[b0i];
                float2 r1 = *(const float2*)&resid[b1i];
                *(float2*)&C[b0i] = make_float2(fmaf(gr0.x, acc[i][j][0], r0.x),
                                                fmaf(gr0.y, acc[i][j][1], r0.y));
                *(float2*)&C[b1i] = make_float2(fmaf(gr1.x, acc[i][j][2], r1.x),
                                                fmaf(gr1.y, acc[i][j][3], r1.y));
            }
        }
    }
    #undef ASI
    #undef BSI
}

// ---------------- tensor-core flash attention (full branches) ----------------
#define ATT_PS   0
#define ATT_KS   8704
#define ATT_VS   13056
#define ATT_SMEM_BYTES ((8704 + 4352 + 4608) * 4)

__global__ __launch_bounds__(256) void attn_tc_k(const float* __restrict__ Q,
                                                 const float* __restrict__ Km,
                                                 const float* __restrict__ Vm,
                                                 float* __restrict__ O, int branch) {
    extern __shared__ float smf[];
    float* Ps = smf + ATT_PS;
    float* Ks = smf + ATT_KS;
    float* Vs = smf + ATT_VS;
    int tid = threadIdx.x, lane = tid & 31, w = tid >> 5;
    int g = lane >> 2, t = lane & 3;
    int bh = blockIdx.y;
    int b = bh >> 4, h = bh & 15;
    int qb = blockIdx.x * 128;
    int headoff = h * DHc;

    #pragma unroll
    for (int i = 0; i < 8; i++) {
        int seg = tid + i * 256;
        int row = seg >> 4, c4 = (seg & 15) << 2;
        float4 v = *(const float4*)&Q[((size_t)(b * Sc + qb + row)) * Dc + headoff + c4];
        float4 cv = make_float4(to_tf32(v.x), to_tf32(v.y), to_tf32(v.z), to_tf32(v.w));
        *(float4*)&Ps[row * 68 + c4] = cv;
    }
    __syncthreads();

    int r0 = w * 16 + g;
    uint32_t qa[8][4];
    #pragma unroll
    for (int kk = 0; kk < 8; kk++) {
        qa[kk][0] = __float_as_uint(Ps[r0 * 68 + kk * 8 + t]);
        qa[kk][1] = __float_as_uint(Ps[(r0 + 8) * 68 + kk * 8 + t]);
        qa[kk][2] = __float_as_uint(Ps[r0 * 68 + kk * 8 + t + 4]);
        qa[kk][3] = __float_as_uint(Ps[(r0 + 8) * 68 + kk * 8 + t + 4]);
    }

    float m0 = -INFINITY, m1 = -INFINITY, l0 = 0.f, l1 = 0.f;
    float o[8][4];
    #pragma unroll
    for (int j = 0; j < 8; j++)
        #pragma unroll
        for (int r = 0; r < 4; r++) o[j][r] = 0.f;

    int qi0 = qb + r0, qi1 = qi0 + 8;

    for (int kt = 0; kt < Sc; kt += 64) {
        __syncthreads();
        #pragma unroll
        for (int i = 0; i < 4; i++) {
            int seg = tid + i * 256;
            int row = seg >> 4, c4 = (seg & 15) << 2;
            size_t gi = ((size_t)(b * Sc + kt + row)) * Dc + headoff + c4;
            float4 kv = *(const float4*)&Km[gi];
            float4 vv = *(const float4*)&Vm[gi];
            *(float4*)&Ks[row * 68 + c4] =
                make_float4(to_tf32(kv.x), to_tf32(kv.y), to_tf32(kv.z), to_tf32(kv.w));
            *(float4*)&Vs[row * 72 + c4] =
                make_float4(to_tf32(vv.x), to_tf32(vv.y), to_tf32(vv.z), to_tf32(vv.w));
        }
        __syncthreads();

        float sc[8][4];
        #pragma unroll
        for (int jn = 0; jn < 8; jn++)
            #pragma unroll
            for (int r = 0; r < 4; r++) sc[jn][r] = 0.f;
        #pragma unroll
        for (int kk = 0; kk < 8; kk++) {
            #pragma unroll
            for (int jn = 0; jn < 8; jn++) {
                uint32_t b0 = __float_as_uint(Ks[(jn * 8 + g) * 68 + kk * 8 + t]);
                uint32_t b1 = __float_as_uint(Ks[(jn * 8 + g) * 68 + kk * 8 + t + 4]);
                mma_tf32(sc[jn], qa[kk][0], qa[kk][1], qa[kk][2], qa[kk][3], b0, b1);
            }
        }

        float rm0 = m0, rm1 = m1;
        #pragma unroll
        for (int jn = 0; jn < 8; jn++) {
            int kj = kt + jn * 8 + 2 * t;
            float b00 = 0.f, b01 = 0.f, b10 = 0.f, b11 = 0.f;
            if (branch == 0) {
                b00 = -(float)abs(qi0 - kj);     b01 = -(float)abs(qi0 - kj - 1);
                b10 = -(float)abs(qi1 - kj);     b11 = -(float)abs(qi1 - kj - 1);
            }
            sc[jn][0] = fmaf(sc[jn][0], 0.125f, b00);
            sc[jn][1] = fmaf(sc[jn][1], 0.125f, b01);
            sc[jn][2] = fmaf(sc[jn][2], 0.125f, b10);
            sc[jn][3] = fmaf(sc[jn][3], 0.125f, b11);
            rm0 = fmaxf(rm0, fmaxf(sc[jn][0], sc[jn][1]));
            rm1 = fmaxf(rm1, fmaxf(sc[jn][2], sc[jn][3]));
        }
        rm0 = fmaxf(rm0, __shfl_xor_sync(~0u, rm0, 1));
        rm0 = fmaxf(rm0, __shfl_xor_sync(~0u, rm0, 2));
        rm1 = fmaxf(rm1, __shfl_xor_sync(~0u, rm1, 1));
        rm1 = fmaxf(rm1, __shfl_xor_sync(~0u, rm1, 2));
        float corr0 = __expf(m0 - rm0), corr1 = __expf(m1 - rm1);
        m0 = rm0; m1 = rm1;

        float sum0 = 0.f, sum1 = 0.f;
        #pragma unroll
        for (int jn = 0; jn < 8; jn++) {
            float p0 = __expf(sc[jn][0] - m0), p1 = __expf(sc[jn][1] - m0);
            float p2 = __expf(sc[jn][2] - m1), p3 = __expf(sc[jn][3] - m1);
            sum0 += p0 + p1; sum1 += p2 + p3;
            *(float2*)&Ps[r0 * 68 + jn * 8 + 2 * t] =
                make_float2(to_tf32(p0), to_tf32(p1));
            *(float2*)&Ps[(r0 + 8) * 68 + jn * 8 + 2 * t] =
                make_float2(to_tf32(p2), to_tf32(p3));
        }
        sum0 += __shfl_xor_sync(~0u, sum0, 1);
        sum0 += __shfl_xor_sync(~0u, sum0, 2);
        sum1 += __shfl_xor_sync(~0u, sum1, 1);
        sum1 += __shfl_xor_sync(~0u, sum1, 2);
        l0 = fmaf(l0, corr0, sum0);
        l1 = fmaf(l1, corr1, sum1);
        #pragma unroll
        for (int jd = 0; jd < 8; jd++) {
            o[jd][0] *= corr0; o[jd][1] *= corr0;
            o[jd][2] *= corr1; o[jd][3] *= corr1;
        }
        __syncwarp();

        #pragma unroll
        for (int ks = 0; ks < 8; ks++) {
            uint32_t pa0 = __float_as_uint(Ps[r0 * 68 + ks * 8 + t]);
            uint32_t pa1 = __float_as_uint(Ps[(r0 + 8) * 68 + ks * 8 + t]);
            uint32_t pa2 = __float_as_uint(Ps[r0 * 68 + ks * 8 + t + 4]);
            uint32_t pa3 = __float_as_uint(Ps[(r0 + 8) * 68 + ks * 8 + t + 4]);
            #pragma unroll
            for (int jd = 0; jd < 8; jd++) {
                uint32_t vb0 = __float_as_uint(Vs[(ks * 8 + t) * 72 + jd * 8 + g]);
                uint32_t vb1 = __float_as_uint(Vs[(ks * 8 + t + 4) * 72 + jd * 8 + g]);
                mma_tf32(o[jd], pa0, pa1, pa2, pa3, vb0, vb1);
            }
        }
    }

    float inv0 = 1.f / l0, inv1 = 1.f / l1;
    size_t row0g = ((size_t)(b * Sc + qb + r0)) * Dc + headoff;
    size_t row1g = row0g + (size_t)8 * Dc;
    #pragma unroll
    for (int jd = 0; jd < 8; jd++) {
        int col = jd * 8 + 2 * t;
        *(float2*)&O[row0g + col] = make_float2(o[jd][0] * inv0, o[jd][1] * inv0);
        *(float2*)&O[row1g + col] = make_float2(o[jd][2] * inv1, o[jd][3] * inv1);
    }
}

// ---------------- sparse attention for masked branches ----------------
__global__ __launch_bounds__(128) void attn_sparse_k(const float* __restrict__ Q,
                                                     const float* __restrict__ Km,
                                                     const float* __restrict__ Vm,
                                                     float* __restrict__ O, int mode) {
    int w = threadIdx.x >> 5, lane = threadIdx.x & 31;
    int qi = blockIdx.x * 4 + w;
    int bh = blockIdx.y;
    int b = bh >> 4, h = bh & 15;
    size_t rowbase = ((size_t)(b * Sc + qi)) * Dc + (size_t)h * DHc;
    float q0 = Q[rowbase + lane], q1 = Q[rowbase + 32 + lane];

    int k0i, nk;
    if (mode == 1) {
        k0i = qi - 1; nk = 3;
        if (qi == 0)      { k0i = 0; nk = 2; }
        if (qi == Sc - 1) { nk = 2; }
    } else {
        k0i = qi & ~1; nk = 2;
    }

    float s[3] = {0.f, 0.f, 0.f};
    #pragma unroll 3
    for (int kk = 0; kk < 3; kk++) {
        if (kk < nk) {
            size_t kb = ((size_t)(b * Sc + k0i + kk)) * Dc + (size_t)h * DHc;
            float acc = fmaf(q0, Km[kb + lane], q1 * Km[kb + 32 + lane]);
            #pragma unroll
            for (int off = 16; off; off >>= 1)
                acc += __shfl_xor_sync(~0u, acc, off);
            s[kk] = acc * 0.125f;
        }
    }
    float mx = s[0];
    for (int kk = 1; kk < nk; kk++) mx = fmaxf(mx, s[kk]);
    float p[3], l = 0.f;
    for (int kk = 0; kk < nk; kk++) { p[kk] = __expf(s[kk] - mx); l += p[kk]; }
    float inv = 1.f / l;

    float o0 = 0.f, o1 = 0.f;
    #pragma unroll 3
    for (int kk = 0; kk < 3; kk++) {
        if (kk < nk) {
            size_t vb = ((size_t)(b * Sc + k0i + kk)) * Dc + (size_t)h * DHc;
            o0 = fmaf(p[kk], Vm[vb + lane], o0);
            o1 = fmaf(p[kk], Vm[vb + 32 + lane], o1);
        }
    }
    O[rowbase + lane]      = o0 * inv;
    O[rowbase + 32 + lane] = o1 * inv;
}

// ---------------- fusion gate ----------------
__global__ __launch_bounds__(256) void gate_k(const float* __restrict__ Ob,
                                              const float* __restrict__ wg,
                                              const float* __restrict__ bg,
                                              float* __restrict__ gate) {
    int t = blockIdx.x, tid = threadIdx.x;
    float4 acc = make_float4(0.f, 0.f, 0.f, 0.f);
    for (int d = tid; d < 4 * Dc; d += 256) {
        int p = d >> 10, dd = d & 1023;
        float v = Ob[((size_t)p * TOK + t) * Dc + dd];
        float4 wv = *(const float4*)&wg[(size_t)d * 4];
        acc.x = fmaf(v, wv.x, acc.x);
        acc.y = fmaf(v, wv.y, acc.y);
        acc.z = fmaf(v, wv.z, acc.z);
        acc.w = fmaf(v, wv.w, acc.w);
    }
    #pragma unroll
    for (int off = 16; off; off >>= 1) {
        acc.x += __shfl_xor_sync(~0u, acc.x, off);
        acc.y += __shfl_xor_sync(~0u, acc.y, off);
        acc.z += __shfl_xor_sync(~0u, acc.z, off);
        acc.w += __shfl_xor_sync(~0u, acc.w, off);
    }
    __shared__ float4 red[8];
    if ((tid & 31) == 0) red[tid >> 5] = acc;
    __syncthreads();
    if (tid == 0) {
        float4 a = red[0];
        #pragma unroll
        for (int i = 1; i < 8; i++) {
            a.x += red[i].x; a.y += red[i].y; a.z += red[i].z; a.w += red[i].w;
        }
        float l0 = a.x + bg[0], l1 = a.y + bg[1], l2 = a.z + bg[2], l3 = a.w + bg[3];
        float mx = fmaxf(fmaxf(l0, l1), fmaxf(l2, l3));
        float e0 = __expf(l0 - mx), e1 = __expf(l1 - mx),
              e2 = __expf(l2 - mx), e3 = __expf(l3 - mx);
        float inv = 1.f / (e0 + e1 + e2 + e3);
        gate[t * 4 + 0] = e0 * inv; gate[t * 4 + 1] = e1 * inv;
        gate[t * 4 + 2] = e2 * inv; gate[t * 4 + 3] = e3 * inv;
    }
}

__global__ void fusemix_k(const float* __restrict__ Ob,
                          const float* __restrict__ gate,
                          float* __restrict__ out) {
    int idx = blockIdx.x * 256 + threadIdx.x;
    int t = idx >> 10;
    float g0 = gate[t * 4 + 0], g1 = gate[t * 4 + 1];
    float g2 = gate[t * 4 + 2], g3 = gate[t * 4 + 3];
    const size_t P = TOKD;
    out[idx] = to_tf32(g0 * Ob[idx] + g1 * Ob[idx + P] +
                       g2 * Ob[idx + 2 * P] + g3 * Ob[idx + 3 * P]);
}

__global__ void swiglu_k(const float* __restrict__ h1,
                         const float* __restrict__ h3,
                         float* __restrict__ out, size_t n) {
    size_t i = (size_t)blockIdx.x * 256 + threadIdx.x;
    if (i < n) {
        float a = h1[i];
        out[i] = to_tf32((a / (1.f + __expf(-a))) * h3[i]);
    }
}

// ---------------- host launch ----------------
extern "C" void kernel_launch(void* const* d_in, const int* in_sizes, int n_in,
                              void* d_out, int out_size) {
    const float* x      = (const float*)d_in[0];
    const float* t_emb  = (const float*)d_in[1];
    const float* ln1_g  = (const float*)d_in[2];
    const float* ln1_b  = (const float*)d_in[3];
    const float* ln2_g  = (const float*)d_in[4];
    const float* ln2_b  = (const float*)d_in[5];
    const float* ada_w  = (const float*)d_in[6];
    const float* ada_b  = (const float*)d_in[7];

    const float *fus_wg, *fus_bg, *fus_wo, *ffn_w1, *ffn_w2, *ffn_w3;
    int ab;
    if (in_sizes[8] == 16384) {
        fus_wg = (const float*)d_in[8];  fus_bg = (const float*)d_in[9];
        fus_wo = (const float*)d_in[10];
        ffn_w1 = (const float*)d_in[11]; ffn_w2 = (const float*)d_in[12];
        ffn_w3 = (const float*)d_in[13];
        ab = 14;
    } else {
        ab = 8;
        fus_wg = (const float*)d_in[24]; fus_bg = (const float*)d_in[25];
        fus_wo = (const float*)d_in[26];
        ffn_w1 = (const float*)d_in[27]; ffn_w2 = (const float*)d_in[28];
        ffn_w3 = (const float*)d_in[29];
    }

    float *st, *ada, *nx, *wsc, *qkv, *ao4, *obr, *gate, *fused, *xmid, *hh;
    cudaGetSymbolAddress((void**)&st,    g_st);
    cudaGetSymbolAddress((void**)&ada,   g_ada);
    cudaGetSymbolAddress((void**)&nx,    g_nx);
    cudaGetSymbolAddress((void**)&wsc,   g_w);
    cudaGetSymbolAddress((void**)&qkv,   g_qkv);
    cudaGetSymbolAddress((void**)&ao4,   g_ao4);
    cudaGetSymbolAddress((void**)&obr,   g_obr);
    cudaGetSymbolAddress((void**)&gate,  g_gate);
    cudaGetSymbolAddress((void**)&fused, g_fused);
    cudaGetSymbolAddress((void**)&xmid,  g_xmid);
    cudaGetSymbolAddress((void**)&hh,    g_h);
    float* h1 = hh;
    float* h3 = hh + TOKF;

    cudaFuncSetAttribute(attn_tc_k, cudaFuncAttributeMaxDynamicSharedMemorySize,
                         ATT_SMEM_BYTES);
    cudaFuncSetAttribute(gemm_tc, cudaFuncAttributeMaxDynamicSharedMemorySize,
                         GEMM_SMEM);

    float* out = (float*)d_out;

    // 0. pre-round all GEMM weights into scratch
    WPtrs wp;
    for (int p = 0; p < 4; p++) {
        wp.p[p * 3 + 0] = (const float*)d_in[ab + p * 4 + 0];
        wp.p[p * 3 + 1] = (const float*)d_in[ab + p * 4 + 1];
        wp.p[p * 3 + 2] = (const float*)d_in[ab + p * 4 + 2];
        wp.p[12 + p]    = (const float*)d_in[ab + p * 4 + 3];
    }
    wp.p[16] = fus_wo; wp.p[17] = ffn_w1; wp.p[18] = ffn_w3; wp.p[19] = ffn_w2;
    wround_k<<<(unsigned)(((size_t)29 << 20) / 1024), 256>>>(wp, wsc);

    // 1. AdaLN parameters
    silu_k<<<(Bc * Dc + 255) / 256, 256>>>(t_emb, st, Bc * Dc);
    ada_k<<<(Bc * SIXD) / 8, 256>>>(st, ada_w, ada_b, ada);

    // 2. nx = modulated LN(x), tf32-rounded
    ln_mod_k<<<TOK, 256>>>(x, ln1_g, ln1_b, ada, 0, Dc, nx);

    // 3. all 12 QKV projections in one batched launch
    dim3 gQKV(Dc / 128, TOK / 128, 12);
    gemm_tc<<<gQKV, 256, GEMM_SMEM>>>(nx, 0, wsc + WQKV, (size_t)1 << 20,
                                      qkv, TOKD, TOK, Dc, Dc, nullptr, nullptr);

    // 4. four attention branches (into ao4)
    dim3 gAttn(Sc / 128, Bc * Hc);
    dim3 gSparse(Sc / 4, Bc * Hc);
    for (int p = 0; p < 4; p++) {
        const float* q = qkv + (size_t)(3 * p + 0) * TOKD;
        const float* k = qkv + (size_t)(3 * p + 1) * TOKD;
        const float* v = qkv + (size_t)(3 * p + 2) * TOKD;
        float* ao = ao4 + (size_t)p * TOKD;
        if (p == 1 || p == 2)
            attn_sparse_k<<<gSparse, 128>>>(q, k, v, ao, p);
        else
            attn_tc_k<<<gAttn, 256, ATT_SMEM_BYTES>>>(q, k, v, ao, p);
    }

    // 5. four Wo GEMMs batched
    dim3 gWo(Dc / 128, TOK / 128, 4);
    gemm_tc<<<gWo, 256, GEMM_SMEM>>>(ao4, TOKD, wsc + WO, (size_t)1 << 20,
                                     obr, TOKD, TOK, Dc, Dc, nullptr, nullptr);

    // 6. learned fusion + first residual (g_m at 2D)
    dim3 gProj(Dc / 128, TOK / 128, 1);
    gate_k<<<TOK, 256>>>(obr, fus_wg, fus_bg, gate);
    fusemix_k<<<(TOK * Dc) / 256, 256>>>(obr, gate, fused);
    gemm_tc<<<gProj, 256, GEMM_SMEM>>>(fused, 0, wsc + WFUS, 0, xmid, 0,
                                       TOK, Dc, Dc, x, ada + 2 * Dc);

    // 7. FFN with AdaLN
    ln_mod_k<<<TOK, 256>>>(xmid, ln2_g, ln2_b, ada, 3 * Dc, 4 * Dc, nx);
    dim3 gFfnUp(Fc / 128, TOK / 128, 2);
    gemm_tc<<<gFfnUp, 256, GEMM_SMEM>>>(nx, 0, wsc + W1, W3 - W1,
                                        h1, TOKF, TOK, Fc, Dc, nullptr, nullptr);
    size_t nf = TOKF;
    swiglu_k<<<(unsigned)((nf + 255) / 256), 256>>>(h1, h3, h1, nf);
    gemm_tc<<<gProj, 256, GEMM_SMEM>>>(h1, 0, wsc + W2, 0, out, 0,
                                       TOK, Dc, Fc, xmid, ada + 5 * Dc);
}